// round 3
// baseline (speedup 1.0000x reference)
#include <cuda_runtime.h>
#include <cuda_bf16.h>
#include <math.h>
#include <stdint.h>

#define T_TOK   32768
#define H_DIM   256
#define F_DIM   512
#define E_NUM   16
#define ROWS_PAD 67584            // 2*T + E*128 worst-case padding
#define MAXT    (ROWS_PAD / 128)  // 528 m-tiles

// ---------------- scratch ----------------
__device__ int   g_counts[E_NUM];
__device__ int   g_cursor[E_NUM];
__device__ int   g_poff[E_NUM + 1];
__device__ int   g_eid[T_TOK * 2];
__device__ float g_gw[T_TOK * 2];
__device__ int   g_rowtok[ROWS_PAD];
__device__ int   g_tokrow[T_TOK * 2];
__device__ __nv_bfloat16 g_xb[(size_t)T_TOK * H_DIM];          // x in bf16
__device__ __nv_bfloat16 g_h[(size_t)ROWS_PAD * F_DIM];        // hidden (bf16)
__device__ float g_eout[(size_t)ROWS_PAD * H_DIM];             // expert out (fp32)
__device__ __nv_bfloat16 g_w1t[(size_t)E_NUM * F_DIM * H_DIM]; // [E][N=F][K=H]
__device__ __nv_bfloat16 g_w2t[(size_t)E_NUM * H_DIM * F_DIM]; // [E][N=H][K=F]

// ---------------- helpers ----------------
__device__ __forceinline__ uint32_t smem_u32(const void* p) {
    uint32_t a;
    asm("{ .reg .u64 t; cvta.to.shared.u64 t, %1; cvt.u32.u64 %0, t; }" : "=r"(a) : "l"(p));
    return a;
}
__device__ __forceinline__ uint32_t packbf(float a, float b) {
    __nv_bfloat162 t = __floats2bfloat162_rn(a, b);
    return reinterpret_cast<uint32_t&>(t);
}
#define CP_ASYNC16(dst, src) \
    asm volatile("cp.async.cg.shared.global [%0], [%1], 16;" :: "r"(dst), "l"(src) : "memory")
#define CP_COMMIT() asm volatile("cp.async.commit_group;" ::: "memory")
#define CP_WAIT0()  asm volatile("cp.async.wait_group 0;" ::: "memory")
#define CP_WAIT1()  asm volatile("cp.async.wait_group 1;" ::: "memory")
#define LDSM4(r0, r1, r2, r3, a) \
    asm volatile("ldmatrix.sync.aligned.m8n8.x4.shared.b16 {%0,%1,%2,%3}, [%4];" \
        : "=r"(r0), "=r"(r1), "=r"(r2), "=r"(r3) : "r"(a))
#define MMA16816(d, a, b0v, b1v) \
    asm volatile("mma.sync.aligned.m16n8k16.row.col.f32.bf16.bf16.f32 " \
        "{%0,%1,%2,%3}, {%4,%5,%6,%7}, {%8,%9}, {%0,%1,%2,%3};" \
        : "+f"((d)[0]), "+f"((d)[1]), "+f"((d)[2]), "+f"((d)[3]) \
        : "r"((a)[0]), "r"((a)[1]), "r"((a)[2]), "r"((a)[3]), "r"(b0v), "r"(b1v))

// ---------------- init ----------------
__global__ void k_init() {
    int i = blockIdx.x * blockDim.x + threadIdx.x;
    if (i < ROWS_PAD) g_rowtok[i] = -1;
    if (i < E_NUM) { g_counts[i] = 0; g_cursor[i] = 0; }
}

// ---------------- x -> bf16 ----------------
__global__ void k_xb(const float* __restrict__ x) {
    int i = blockIdx.x * blockDim.x + threadIdx.x;   // one per 8 elems
    const float4* s = (const float4*)(x) + i * 2;
    float4 u0 = s[0], u1 = s[1];
    uint4 o;
    o.x = packbf(u0.x, u0.y); o.y = packbf(u0.z, u0.w);
    o.z = packbf(u1.x, u1.y); o.w = packbf(u1.z, u1.w);
    ((uint4*)g_xb)[i] = o;
}

// ---------------- gating ----------------
__global__ void k_gate(const float* __restrict__ x, const float* __restrict__ gw,
                       const float* __restrict__ gb) {
    __shared__ float sgw[H_DIM * 17];
    int tid = threadIdx.x;
    for (int i = tid; i < H_DIM * E_NUM; i += 256) {
        int h = i >> 4, e = i & 15;
        sgw[h * 17 + e] = gw[i];
    }
    __syncthreads();
    int warp = tid >> 5, lane = tid & 31;
    int t = blockIdx.x * 8 + warp;
    float acc[E_NUM];
#pragma unroll
    for (int e = 0; e < E_NUM; e++) acc[e] = 0.f;
    const float* xr = x + (size_t)t * H_DIM;
#pragma unroll
    for (int c = 0; c < H_DIM / 32; c++) {
        int h = c * 32 + lane;
        float xv = xr[h];
#pragma unroll
        for (int e = 0; e < E_NUM; e++) acc[e] += xv * sgw[h * 17 + e];
    }
#pragma unroll
    for (int e = 0; e < E_NUM; e++) {
        float v = acc[e];
        v += __shfl_down_sync(0xffffffffu, v, 16);
        v += __shfl_down_sync(0xffffffffu, v, 8);
        v += __shfl_down_sync(0xffffffffu, v, 4);
        v += __shfl_down_sync(0xffffffffu, v, 2);
        v += __shfl_down_sync(0xffffffffu, v, 1);
        acc[e] = v;
    }
    if (lane == 0) {
        float logit[E_NUM];
#pragma unroll
        for (int e = 0; e < E_NUM; e++) logit[e] = acc[e] + gb[e];
        int i0 = 0; float m0 = logit[0];
#pragma unroll
        for (int e = 1; e < E_NUM; e++) if (logit[e] > m0) { m0 = logit[e]; i0 = e; }
        int i1 = -1; float m1 = -3.0e38f;
#pragma unroll
        for (int e = 0; e < E_NUM; e++)
            if (e != i0 && logit[e] > m1) { m1 = logit[e]; i1 = e; }
        float z = expf(m1 - m0);
        float w0 = 1.f / (1.f + z);
        float w1 = z * w0;
        g_eid[t * 2 + 0] = i0; g_eid[t * 2 + 1] = i1;
        g_gw[t * 2 + 0] = w0;  g_gw[t * 2 + 1] = w1;
        atomicAdd(&g_counts[i0], 1);
        atomicAdd(&g_counts[i1], 1);
    }
}

__global__ void k_scan() {
    if (threadIdx.x == 0) {
        int off = 0;
        g_poff[0] = 0;
        for (int e = 0; e < E_NUM; e++) {
            off += (g_counts[e] + 127) & ~127;
            g_poff[e + 1] = off;
        }
    }
}

__global__ void k_scatter() {
    int t = blockIdx.x * blockDim.x + threadIdx.x;
    if (t >= T_TOK) return;
#pragma unroll
    for (int k = 0; k < 2; k++) {
        int e = g_eid[t * 2 + k];
        int pos = atomicAdd(&g_cursor[e], 1);
        int row = g_poff[e] + pos;
        g_rowtok[row] = t;
        g_tokrow[t * 2 + k] = row;
    }
}

// ---------------- weight transpose + bf16: W[E][R][C] -> Wt[E][C][R] ----------------
__global__ void k_wt(const float* __restrict__ W, __nv_bfloat16* __restrict__ Wt,
                     int R, int C) {
    __shared__ float t[32][33];
    int e = blockIdx.z;
    int c0 = blockIdx.x * 32, r0 = blockIdx.y * 32;
    const float* Wb = W + (size_t)e * R * C;
    __nv_bfloat16* Tb = Wt + (size_t)e * R * C;
    int x = threadIdx.x, y = threadIdx.y;
#pragma unroll
    for (int i = 0; i < 32; i += 8)
        t[y + i][x] = Wb[(size_t)(r0 + y + i) * C + c0 + x];
    __syncthreads();
#pragma unroll
    for (int i = 0; i < 32; i += 8)
        Tb[(size_t)(c0 + y + i) * R + r0 + x] = __float2bfloat16(t[x][y + i]);
}

// ---------------- bf16 HMMA grouped GEMM ----------------
// Block tile 128(M) x 128(N); K in 64-elem chunks; 8 warps as 2x4 -> warp tile 64x32.
// A[128 x K] from gathered g_xb rows (GATHER) or g_h rows; B = Wt[e] ([N][K], k-contig).
#define SMEM_DYN (1024 + 4 * 16384)

template <int KDIM, int NDIM, bool GATHER, bool RELU>
__global__ void __launch_bounds__(256)
k_mma(const __nv_bfloat16* __restrict__ Wt, const float* __restrict__ bias) {
    constexpr int CHUNKS = KDIM / 64;

    extern __shared__ char dsm[];
    const __nv_bfloat16** rowp = (const __nv_bfloat16**)dsm;   // [128]
    char* sbase = dsm;
    uint32_t sb = smem_u32(sbase);
    const uint32_t OFF_A[2] = {1024u, 1024u + 16384u};
    const uint32_t OFF_B[2] = {1024u + 32768u, 1024u + 49152u};

    int tid = threadIdx.x, wid = tid >> 5, lane = tid & 31;
    int total = g_poff[E_NUM];
    int r0 = blockIdx.x * 128;
    if (r0 >= total) return;
    int e = 0;
#pragma unroll
    for (int i = 1; i < E_NUM; i++) if (r0 >= g_poff[i]) e = i;
    int n0 = blockIdx.y * 128;
    const __nv_bfloat16* Wb = Wt + (size_t)e * NDIM * KDIM + (size_t)n0 * KDIM;

    // row pointer table
    if (tid < 128) {
        if (GATHER) {
            int tok = g_rowtok[r0 + tid];
            rowp[tid] = g_xb + (size_t)(tok < 0 ? 0 : tok) * KDIM;
        } else {
            rowp[tid] = g_h + (size_t)(r0 + tid) * KDIM;
        }
    }
    __syncthreads();

    // cp.async slot assignment: 1024 16B-slots per tile; thread does 4 (A) + 4 (B)
    int srow = tid >> 1;                 // 0..127, two threads per row
    int skb0 = (tid & 1) * 4;            // kb 0..3 or 4..7
    uint32_t dstA_base = sb + (uint32_t)srow * 128;
    const int swz_r = (srow & 7);

    int warpm = wid & 1, warpn = wid >> 1;
    int l8 = lane & 7, g2 = lane >> 3;
    int row_in_mat = l8 + (g2 & 1) * 8;
    int colhalf = g2 >> 1;
    // ldmatrix lane-constant pieces
    uint32_t a_lanebase = sb + (uint32_t)(warpm * 64 + row_in_mat) * 128;
    uint32_t b_lanebase = sb + (uint32_t)(warpn * 32 + row_in_mat) * 128;
    int swz_lane = l8 * 16;
    int ch16 = colhalf * 16;

    float acc[4][4][4];
#pragma unroll
    for (int mt = 0; mt < 4; mt++)
#pragma unroll
        for (int nn = 0; nn < 4; nn++)
#pragma unroll
            for (int q = 0; q < 4; q++) acc[mt][nn][q] = 0.f;

    // ---- prologue: load chunk 0 ----
    {
        const __nv_bfloat16* ap = rowp[srow];
        const __nv_bfloat16* bp = Wb + (size_t)srow * KDIM;
#pragma unroll
        for (int i = 0; i < 4; i++) {
            int kb = skb0 + i;
            uint32_t dsw = (uint32_t)((kb ^ swz_r) * 16);
            CP_ASYNC16(dstA_base + OFF_A[0] + dsw, ap + kb * 8);
            CP_ASYNC16(dstA_base + OFF_B[0] + dsw, bp + kb * 8);
        }
        CP_COMMIT();
    }

#pragma unroll
    for (int c = 0; c < CHUNKS; c++) {
        const int b = c & 1;
        if (c + 1 < CHUNKS) {
            const __nv_bfloat16* ap = rowp[srow] + (c + 1) * 64;
            const __nv_bfloat16* bp = Wb + (size_t)srow * KDIM + (c + 1) * 64;
            const int nb = (c + 1) & 1;
#pragma unroll
            for (int i = 0; i < 4; i++) {
                int kb = skb0 + i;
                uint32_t dsw = (uint32_t)((kb ^ swz_r) * 16);
                CP_ASYNC16(dstA_base + OFF_A[nb] + dsw, ap + kb * 8);
                CP_ASYNC16(dstA_base + OFF_B[nb] + dsw, bp + kb * 8);
            }
            CP_COMMIT();
            CP_WAIT1();
        } else {
            CP_WAIT0();
        }
        __syncthreads();

        // ---- compute on buffer b ----
        uint32_t abase = a_lanebase + OFF_A[b];
        uint32_t bbase = b_lanebase + OFF_B[b];
#pragma unroll
        for (int ks = 0; ks < 4; ks++) {
            uint32_t koff = (uint32_t)(((ks * 32 + ch16) ^ swz_lane));
            uint32_t af[4][4];
#pragma unroll
            for (int mt = 0; mt < 4; mt++)
                LDSM4(af[mt][0], af[mt][1], af[mt][2], af[mt][3],
                      abase + mt * 2048 + koff);
            uint32_t bf[2][4];
#pragma unroll
            for (int p = 0; p < 2; p++)
                LDSM4(bf[p][0], bf[p][1], bf[p][2], bf[p][3],
                      bbase + p * 2048 + koff);
#pragma unroll
            for (int mt = 0; mt < 4; mt++) {
#pragma unroll
                for (int p = 0; p < 2; p++) {
                    MMA16816(acc[mt][2 * p + 0], af[mt], bf[p][0], bf[p][2]);
                    MMA16816(acc[mt][2 * p + 1], af[mt], bf[p][1], bf[p][3]);
                }
            }
        }
        __syncthreads();
    }

    // ---- epilogue ----
    const float* bp = bias + (size_t)e * NDIM + n0 + warpn * 32;
    float bv[4][2];
#pragma unroll
    for (int nn = 0; nn < 4; nn++) {
        int nc = nn * 8 + (lane & 3) * 2;
        bv[nn][0] = bp[nc];
        bv[nn][1] = bp[nc + 1];
    }
#pragma unroll
    for (int mt = 0; mt < 4; mt++) {
        int r = r0 + warpm * 64 + mt * 16 + (lane >> 2);
#pragma unroll
        for (int nn = 0; nn < 4; nn++) {
            int nc = n0 + warpn * 32 + nn * 8 + (lane & 3) * 2;
            float v0 = acc[mt][nn][0] + bv[nn][0];
            float v1 = acc[mt][nn][1] + bv[nn][1];
            float v2 = acc[mt][nn][2] + bv[nn][0];
            float v3 = acc[mt][nn][3] + bv[nn][1];
            if (RELU) {
                v0 = fmaxf(v0, 0.f); v1 = fmaxf(v1, 0.f);
                v2 = fmaxf(v2, 0.f); v3 = fmaxf(v3, 0.f);
                *(uint32_t*)(g_h + (size_t)r * NDIM + nc) = packbf(v0, v1);
                *(uint32_t*)(g_h + (size_t)(r + 8) * NDIM + nc) = packbf(v2, v3);
            } else {
                *(float2*)(g_eout + (size_t)r * NDIM + nc) = make_float2(v0, v1);
                *(float2*)(g_eout + (size_t)(r + 8) * NDIM + nc) = make_float2(v2, v3);
            }
        }
    }
}

// ---------------- combine + residual + LayerNorm ----------------
__global__ void k_combine_ln(const float* __restrict__ x,
                             const float* __restrict__ gamma,
                             const float* __restrict__ beta,
                             float* __restrict__ out) {
    int warp = threadIdx.x >> 5, lane = threadIdx.x & 31;
    int t = blockIdx.x * 8 + warp;
    int row0 = g_tokrow[t * 2 + 0];
    int row1 = g_tokrow[t * 2 + 1];
    float w0 = g_gw[t * 2 + 0];
    float w1 = g_gw[t * 2 + 1];
    const float* xr = x + (size_t)t * H_DIM;
    const float* o0 = g_eout + (size_t)row0 * H_DIM;
    const float* o1 = g_eout + (size_t)row1 * H_DIM;
    float v[8];
    float s = 0.f, sq = 0.f;
#pragma unroll
    for (int j = 0; j < 8; j++) {
        int h = j * 32 + lane;
        float y = xr[h] + w0 * o0[h] + w1 * o1[h];
        v[j] = y;
        s += y;
        sq += y * y;
    }
#pragma unroll
    for (int off = 16; off > 0; off >>= 1) {
        s  += __shfl_xor_sync(0xffffffffu, s, off);
        sq += __shfl_xor_sync(0xffffffffu, sq, off);
    }
    float mu = s * (1.f / H_DIM);
    float var = sq * (1.f / H_DIM) - mu * mu;
    float rs = rsqrtf(var + 1e-5f);
    float* outr = out + (size_t)t * H_DIM;
#pragma unroll
    for (int j = 0; j < 8; j++) {
        int h = j * 32 + lane;
        outr[h] = (v[j] - mu) * rs * gamma[h] + beta[h];
    }
}

// ---------------- launch ----------------
extern "C" void kernel_launch(void* const* d_in, const int* in_sizes, int n_in,
                              void* d_out, int out_size) {
    const float* x      = (const float*)d_in[0];
    const float* gate_w = (const float*)d_in[1];
    const float* gate_b = (const float*)d_in[2];
    const float* w1     = (const float*)d_in[3];
    const float* b1     = (const float*)d_in[4];
    const float* w2     = (const float*)d_in[5];
    const float* b2     = (const float*)d_in[6];
    const float* gamma  = (const float*)d_in[7];
    const float* beta   = (const float*)d_in[8];
    float* out = (float*)d_out;

    cudaFuncSetAttribute((const void*)k_mma<H_DIM, F_DIM, true, true>,
                         cudaFuncAttributeMaxDynamicSharedMemorySize, SMEM_DYN);
    cudaFuncSetAttribute((const void*)k_mma<F_DIM, H_DIM, false, false>,
                         cudaFuncAttributeMaxDynamicSharedMemorySize, SMEM_DYN);

    k_init<<<(ROWS_PAD + 255) / 256, 256>>>();
    k_xb<<<T_TOK * H_DIM / 8 / 256, 256>>>(x);
    k_gate<<<T_TOK / 8, 256>>>(x, gate_w, gate_b);
    k_scan<<<1, 32>>>();
    k_scatter<<<T_TOK / 256, 256>>>();
    k_wt<<<dim3(F_DIM / 32, H_DIM / 32, E_NUM), dim3(32, 8)>>>(w1, g_w1t, H_DIM, F_DIM);
    k_wt<<<dim3(H_DIM / 32, F_DIM / 32, E_NUM), dim3(32, 8)>>>(w2, g_w2t, F_DIM, H_DIM);
    k_mma<H_DIM, F_DIM, true,  true ><<<dim3(MAXT, F_DIM / 128), 256, SMEM_DYN>>>(g_w1t, b1);
    k_mma<F_DIM, H_DIM, false, false><<<dim3(MAXT, H_DIM / 128), 256, SMEM_DYN>>>(g_w2t, b2);
    k_combine_ln<<<T_TOK / 8, 256>>>(x, gamma, beta, out);
}

// round 4
// speedup vs baseline: 1.2074x; 1.2074x over previous
#include <cuda_runtime.h>
#include <cuda_bf16.h>
#include <math.h>
#include <stdint.h>

#define T_TOK   32768
#define H_DIM   256
#define F_DIM   512
#define E_NUM   16
#define ROWS_PAD 67584            // 2*T + E*128 worst-case padding
#define MAXT    (ROWS_PAD / 128)  // 528 m-tiles

// ---------------- scratch ----------------
__device__ int   g_counts[E_NUM];
__device__ int   g_cursor[E_NUM];
__device__ int   g_poff[E_NUM + 1];
__device__ int   g_eid[T_TOK * 2];
__device__ float g_gw[T_TOK * 2];
__device__ int   g_rowtok[ROWS_PAD];
__device__ int   g_tokrow[T_TOK * 2];
__device__ __nv_bfloat16 g_xb[(size_t)T_TOK * H_DIM];          // x in bf16
__device__ __nv_bfloat16 g_h[(size_t)ROWS_PAD * F_DIM];        // hidden (bf16)
__device__ float g_eout[(size_t)ROWS_PAD * H_DIM];             // expert out (fp32)
__device__ __nv_bfloat16 g_w1t[(size_t)E_NUM * F_DIM * H_DIM]; // [E][N=F][K=H]
__device__ __nv_bfloat16 g_w2t[(size_t)E_NUM * H_DIM * F_DIM]; // [E][N=H][K=F]

// ---------------- helpers ----------------
__device__ __forceinline__ uint32_t smem_u32(const void* p) {
    uint32_t a;
    asm("{ .reg .u64 t; cvta.to.shared.u64 t, %1; cvt.u32.u64 %0, t; }" : "=r"(a) : "l"(p));
    return a;
}
__device__ __forceinline__ uint32_t packbf(float a, float b) {
    __nv_bfloat162 t = __floats2bfloat162_rn(a, b);
    return reinterpret_cast<uint32_t&>(t);
}
#define CP_ASYNC16(dst, src) \
    asm volatile("cp.async.cg.shared.global [%0], [%1], 16;" :: "r"(dst), "l"(src) : "memory")
#define CP_COMMIT() asm volatile("cp.async.commit_group;" ::: "memory")
#define CP_WAIT0()  asm volatile("cp.async.wait_group 0;" ::: "memory")
#define CP_WAIT1()  asm volatile("cp.async.wait_group 1;" ::: "memory")
#define LDSM4(r0, r1, r2, r3, a) \
    asm volatile("ldmatrix.sync.aligned.m8n8.x4.shared.b16 {%0,%1,%2,%3}, [%4];" \
        : "=r"(r0), "=r"(r1), "=r"(r2), "=r"(r3) : "r"(a))
#define MMA16816(d, a, b0v, b1v) \
    asm volatile("mma.sync.aligned.m16n8k16.row.col.f32.bf16.bf16.f32 " \
        "{%0,%1,%2,%3}, {%4,%5,%6,%7}, {%8,%9}, {%0,%1,%2,%3};" \
        : "+f"((d)[0]), "+f"((d)[1]), "+f"((d)[2]), "+f"((d)[3]) \
        : "r"((a)[0]), "r"((a)[1]), "r"((a)[2]), "r"((a)[3]), "r"(b0v), "r"(b1v))

// ---------------- init ----------------
__global__ void k_init() {
    int i = blockIdx.x * blockDim.x + threadIdx.x;
    if (i < ROWS_PAD) g_rowtok[i] = -1;
    if (i < E_NUM) { g_counts[i] = 0; g_cursor[i] = 0; }
}

// ---------------- x -> bf16 ----------------
__global__ void k_xb(const float* __restrict__ x) {
    int i = blockIdx.x * blockDim.x + threadIdx.x;
    const float4* s = (const float4*)(x) + i * 2;
    float4 u0 = s[0], u1 = s[1];
    uint4 o;
    o.x = packbf(u0.x, u0.y); o.y = packbf(u0.z, u0.w);
    o.z = packbf(u1.x, u1.y); o.w = packbf(u1.z, u1.w);
    ((uint4*)g_xb)[i] = o;
}

// ---------------- gating ----------------
__global__ void k_gate(const float* __restrict__ x, const float* __restrict__ gw,
                       const float* __restrict__ gb) {
    __shared__ float sgw[H_DIM * 17];
    int tid = threadIdx.x;
    for (int i = tid; i < H_DIM * E_NUM; i += 256) {
        int h = i >> 4, e = i & 15;
        sgw[h * 17 + e] = gw[i];
    }
    __syncthreads();
    int warp = tid >> 5, lane = tid & 31;
    int t = blockIdx.x * 8 + warp;
    float acc[E_NUM];
#pragma unroll
    for (int e = 0; e < E_NUM; e++) acc[e] = 0.f;
    const float* xr = x + (size_t)t * H_DIM;
#pragma unroll
    for (int c = 0; c < H_DIM / 32; c++) {
        int h = c * 32 + lane;
        float xv = xr[h];
#pragma unroll
        for (int e = 0; e < E_NUM; e++) acc[e] += xv * sgw[h * 17 + e];
    }
#pragma unroll
    for (int e = 0; e < E_NUM; e++) {
        float v = acc[e];
        v += __shfl_down_sync(0xffffffffu, v, 16);
        v += __shfl_down_sync(0xffffffffu, v, 8);
        v += __shfl_down_sync(0xffffffffu, v, 4);
        v += __shfl_down_sync(0xffffffffu, v, 2);
        v += __shfl_down_sync(0xffffffffu, v, 1);
        acc[e] = v;
    }
    if (lane == 0) {
        float logit[E_NUM];
#pragma unroll
        for (int e = 0; e < E_NUM; e++) logit[e] = acc[e] + gb[e];
        int i0 = 0; float m0 = logit[0];
#pragma unroll
        for (int e = 1; e < E_NUM; e++) if (logit[e] > m0) { m0 = logit[e]; i0 = e; }
        int i1 = -1; float m1 = -3.0e38f;
#pragma unroll
        for (int e = 0; e < E_NUM; e++)
            if (e != i0 && logit[e] > m1) { m1 = logit[e]; i1 = e; }
        float z = expf(m1 - m0);
        float w0 = 1.f / (1.f + z);
        float w1 = z * w0;
        g_eid[t * 2 + 0] = i0; g_eid[t * 2 + 1] = i1;
        g_gw[t * 2 + 0] = w0;  g_gw[t * 2 + 1] = w1;
        atomicAdd(&g_counts[i0], 1);
        atomicAdd(&g_counts[i1], 1);
    }
}

__global__ void k_scan() {
    if (threadIdx.x == 0) {
        int off = 0;
        g_poff[0] = 0;
        for (int e = 0; e < E_NUM; e++) {
            off += (g_counts[e] + 127) & ~127;
            g_poff[e + 1] = off;
        }
    }
}

__global__ void k_scatter() {
    int t = blockIdx.x * blockDim.x + threadIdx.x;
    if (t >= T_TOK) return;
#pragma unroll
    for (int k = 0; k < 2; k++) {
        int e = g_eid[t * 2 + k];
        int pos = atomicAdd(&g_cursor[e], 1);
        int row = g_poff[e] + pos;
        g_rowtok[row] = t;
        g_tokrow[t * 2 + k] = row;
    }
}

// ---------------- weight transpose + bf16: W[E][R][C] -> Wt[E][C][R] ----------------
__global__ void k_wt(const float* __restrict__ W, __nv_bfloat16* __restrict__ Wt,
                     int R, int C) {
    __shared__ float t[32][33];
    int e = blockIdx.z;
    int c0 = blockIdx.x * 32, r0 = blockIdx.y * 32;
    const float* Wb = W + (size_t)e * R * C;
    __nv_bfloat16* Tb = Wt + (size_t)e * R * C;
    int x = threadIdx.x, y = threadIdx.y;
#pragma unroll
    for (int i = 0; i < 32; i += 8)
        t[y + i][x] = Wb[(size_t)(r0 + y + i) * C + c0 + x];
    __syncthreads();
#pragma unroll
    for (int i = 0; i < 32; i += 8)
        Tb[(size_t)(c0 + y + i) * R + r0 + x] = __float2bfloat16(t[x][y + i]);
}

// ---------------- bf16 HMMA grouped GEMM ----------------
// Block tile 128(M) x 64(N); 8 warps as 4(M) x 2(N) -> warp tile 32x32.
// 32 accumulators/thread, ~80 regs -> 3 CTAs/SM.
#define SMEM_DYN (1024 + 2 * 16384 + 2 * 8192)

template <int KDIM, int NDIM, bool GATHER, bool RELU>
__global__ void __launch_bounds__(256)
k_mma(const __nv_bfloat16* __restrict__ Wt, const float* __restrict__ bias) {
    constexpr int CHUNKS = KDIM / 64;

    extern __shared__ char dsm[];
    const __nv_bfloat16** rowp = (const __nv_bfloat16**)dsm;   // [128]
    uint32_t sb = smem_u32(dsm);
    const uint32_t OFF_A[2] = {1024u, 1024u + 16384u};
    const uint32_t OFF_B[2] = {33792u, 33792u + 8192u};

    int tid = threadIdx.x, wid = tid >> 5, lane = tid & 31;
    int total = g_poff[E_NUM];
    int r0 = blockIdx.x * 128;
    if (r0 >= total) return;
    int e = 0;
#pragma unroll
    for (int i = 1; i < E_NUM; i++) if (r0 >= g_poff[i]) e = i;
    int n0 = blockIdx.y * 64;
    const __nv_bfloat16* Wb = Wt + (size_t)e * NDIM * KDIM + (size_t)n0 * KDIM;

    if (tid < 128) {
        if (GATHER) {
            int tok = g_rowtok[r0 + tid];
            rowp[tid] = g_xb + (size_t)(tok < 0 ? 0 : tok) * KDIM;
        } else {
            rowp[tid] = g_h + (size_t)(r0 + tid) * KDIM;
        }
    }
    __syncthreads();

    // cp.async assignments
    int srowA = tid >> 1, kbA0 = (tid & 1) * 4, swzA = srowA & 7;       // 4 ops
    int srowB = tid >> 2, kbB0 = (tid & 3) * 2, swzB = srowB & 7;       // 2 ops
    const __nv_bfloat16* rowpA = rowp[srowA];
    const __nv_bfloat16* WbRow = Wb + (size_t)srowB * KDIM;
    uint32_t dstA = sb + (uint32_t)srowA * 128;
    uint32_t dstB = sb + (uint32_t)srowB * 128;

    // fragment lane mapping
    int warpm = wid & 3, warpn = wid >> 2;
    int l8 = lane & 7, g2 = lane >> 3;
    int row_in_mat = l8 + (g2 & 1) * 8;
    int colhalf = g2 >> 1;
    uint32_t a_lanebase = sb + (uint32_t)(warpm * 32 + row_in_mat) * 128;
    uint32_t b_lanebase = sb + (uint32_t)(warpn * 32 + row_in_mat) * 128;

    float acc[2][4][4];
#pragma unroll
    for (int mt = 0; mt < 2; mt++)
#pragma unroll
        for (int nn = 0; nn < 4; nn++)
#pragma unroll
            for (int q = 0; q < 4; q++) acc[mt][nn][q] = 0.f;

    // prologue: chunk 0
    {
#pragma unroll
        for (int i = 0; i < 4; i++) {
            int kb = kbA0 + i;
            CP_ASYNC16(dstA + OFF_A[0] + (uint32_t)((kb ^ swzA) * 16), rowpA + kb * 8);
        }
#pragma unroll
        for (int i = 0; i < 2; i++) {
            int kb = kbB0 + i;
            CP_ASYNC16(dstB + OFF_B[0] + (uint32_t)((kb ^ swzB) * 16), WbRow + kb * 8);
        }
        CP_COMMIT();
    }

#pragma unroll
    for (int c = 0; c < CHUNKS; c++) {
        const int b = c & 1;
        if (c + 1 < CHUNKS) {
            const int nb = (c + 1) & 1;
            const __nv_bfloat16* ap = rowpA + (c + 1) * 64;
            const __nv_bfloat16* bp = WbRow + (c + 1) * 64;
#pragma unroll
            for (int i = 0; i < 4; i++) {
                int kb = kbA0 + i;
                CP_ASYNC16(dstA + OFF_A[nb] + (uint32_t)((kb ^ swzA) * 16), ap + kb * 8);
            }
#pragma unroll
            for (int i = 0; i < 2; i++) {
                int kb = kbB0 + i;
                CP_ASYNC16(dstB + OFF_B[nb] + (uint32_t)((kb ^ swzB) * 16), bp + kb * 8);
            }
            CP_COMMIT();
            CP_WAIT1();
        } else {
            CP_WAIT0();
        }
        __syncthreads();

        uint32_t abase = a_lanebase + OFF_A[b];
        uint32_t bbase = b_lanebase + OFF_B[b];
#pragma unroll
        for (int ks = 0; ks < 4; ks++) {
            uint32_t koff = (uint32_t)(((ks * 2 + colhalf) ^ l8) * 16);
            uint32_t af[2][4];
#pragma unroll
            for (int mt = 0; mt < 2; mt++)
                LDSM4(af[mt][0], af[mt][1], af[mt][2], af[mt][3],
                      abase + mt * 2048 + koff);
            uint32_t bf[2][4];
#pragma unroll
            for (int p = 0; p < 2; p++)
                LDSM4(bf[p][0], bf[p][1], bf[p][2], bf[p][3],
                      bbase + p * 2048 + koff);
#pragma unroll
            for (int mt = 0; mt < 2; mt++) {
#pragma unroll
                for (int p = 0; p < 2; p++) {
                    MMA16816(acc[mt][2 * p + 0], af[mt], bf[p][0], bf[p][2]);
                    MMA16816(acc[mt][2 * p + 1], af[mt], bf[p][1], bf[p][3]);
                }
            }
        }
        __syncthreads();
    }

    // ---- epilogue ----
    const float* bp = bias + (size_t)e * NDIM + n0 + warpn * 32;
    float bv[4][2];
#pragma unroll
    for (int nn = 0; nn < 4; nn++) {
        int nc = nn * 8 + (lane & 3) * 2;
        bv[nn][0] = bp[nc];
        bv[nn][1] = bp[nc + 1];
    }
#pragma unroll
    for (int mt = 0; mt < 2; mt++) {
        int r = r0 + warpm * 32 + mt * 16 + (lane >> 2);
#pragma unroll
        for (int nn = 0; nn < 4; nn++) {
            int nc = n0 + warpn * 32 + nn * 8 + (lane & 3) * 2;
            float v0 = acc[mt][nn][0] + bv[nn][0];
            float v1 = acc[mt][nn][1] + bv[nn][1];
            float v2 = acc[mt][nn][2] + bv[nn][0];
            float v3 = acc[mt][nn][3] + bv[nn][1];
            if (RELU) {
                v0 = fmaxf(v0, 0.f); v1 = fmaxf(v1, 0.f);
                v2 = fmaxf(v2, 0.f); v3 = fmaxf(v3, 0.f);
                *(uint32_t*)(g_h + (size_t)r * NDIM + nc) = packbf(v0, v1);
                *(uint32_t*)(g_h + (size_t)(r + 8) * NDIM + nc) = packbf(v2, v3);
            } else {
                *(float2*)(g_eout + (size_t)r * NDIM + nc) = make_float2(v0, v1);
                *(float2*)(g_eout + (size_t)(r + 8) * NDIM + nc) = make_float2(v2, v3);
            }
        }
    }
}

// ---------------- combine + residual + LayerNorm ----------------
__global__ void k_combine_ln(const float* __restrict__ x,
                             const float* __restrict__ gamma,
                             const float* __restrict__ beta,
                             float* __restrict__ out) {
    int warp = threadIdx.x >> 5, lane = threadIdx.x & 31;
    int t = blockIdx.x * 8 + warp;
    int row0 = g_tokrow[t * 2 + 0];
    int row1 = g_tokrow[t * 2 + 1];
    float w0 = g_gw[t * 2 + 0];
    float w1 = g_gw[t * 2 + 1];
    const float* xr = x + (size_t)t * H_DIM;
    const float* o0 = g_eout + (size_t)row0 * H_DIM;
    const float* o1 = g_eout + (size_t)row1 * H_DIM;
    float v[8];
    float s = 0.f, sq = 0.f;
#pragma unroll
    for (int j = 0; j < 8; j++) {
        int h = j * 32 + lane;
        float y = xr[h] + w0 * o0[h] + w1 * o1[h];
        v[j] = y;
        s += y;
        sq += y * y;
    }
#pragma unroll
    for (int off = 16; off > 0; off >>= 1) {
        s  += __shfl_xor_sync(0xffffffffu, s, off);
        sq += __shfl_xor_sync(0xffffffffu, sq, off);
    }
    float mu = s * (1.f / H_DIM);
    float var = sq * (1.f / H_DIM) - mu * mu;
    float rs = rsqrtf(var + 1e-5f);
    float* outr = out + (size_t)t * H_DIM;
#pragma unroll
    for (int j = 0; j < 8; j++) {
        int h = j * 32 + lane;
        outr[h] = (v[j] - mu) * rs * gamma[h] + beta[h];
    }
}

// ---------------- launch ----------------
extern "C" void kernel_launch(void* const* d_in, const int* in_sizes, int n_in,
                              void* d_out, int out_size) {
    const float* x      = (const float*)d_in[0];
    const float* gate_w = (const float*)d_in[1];
    const float* gate_b = (const float*)d_in[2];
    const float* w1     = (const float*)d_in[3];
    const float* b1     = (const float*)d_in[4];
    const float* w2     = (const float*)d_in[5];
    const float* b2     = (const float*)d_in[6];
    const float* gamma  = (const float*)d_in[7];
    const float* beta   = (const float*)d_in[8];
    float* out = (float*)d_out;

    cudaFuncSetAttribute((const void*)k_mma<H_DIM, F_DIM, true, true>,
                         cudaFuncAttributeMaxDynamicSharedMemorySize, SMEM_DYN);
    cudaFuncSetAttribute((const void*)k_mma<F_DIM, H_DIM, false, false>,
                         cudaFuncAttributeMaxDynamicSharedMemorySize, SMEM_DYN);

    k_init<<<(ROWS_PAD + 255) / 256, 256>>>();
    k_xb<<<T_TOK * H_DIM / 8 / 256, 256>>>(x);
    k_gate<<<T_TOK / 8, 256>>>(x, gate_w, gate_b);
    k_scan<<<1, 32>>>();
    k_scatter<<<T_TOK / 256, 256>>>();
    k_wt<<<dim3(F_DIM / 32, H_DIM / 32, E_NUM), dim3(32, 8)>>>(w1, g_w1t, H_DIM, F_DIM);
    k_wt<<<dim3(H_DIM / 32, F_DIM / 32, E_NUM), dim3(32, 8)>>>(w2, g_w2t, F_DIM, H_DIM);
    k_mma<H_DIM, F_DIM, true,  true ><<<dim3(MAXT, F_DIM / 64), 256, SMEM_DYN>>>(g_w1t, b1);
    k_mma<F_DIM, H_DIM, false, false><<<dim3(MAXT, H_DIM / 64), 256, SMEM_DYN>>>(g_w2t, b2);
    k_combine_ln<<<T_TOK / 8, 256>>>(x, gamma, beta, out);
}

// round 5
// speedup vs baseline: 4.6035x; 3.8127x over previous
#include <cuda_runtime.h>
#include <math.h>
#include <stdint.h>

#define T_TOK   32768
#define H_DIM   256
#define F_DIM   512
#define E_NUM   16
#define ROWS_PAD 67584            // 2*T + E*128 (worst-case segment padding)
#define MAXT    (ROWS_PAD / 128)  // 528 m-tiles

// ---------------- scratch ----------------
__device__ int   g_counts[E_NUM];
__device__ int   g_cursor[E_NUM];
__device__ int   g_poff[E_NUM + 1];
__device__ int   g_eid[T_TOK * 2];
__device__ float g_gw[T_TOK * 2];
__device__ int   g_rowtok[ROWS_PAD];
__device__ int   g_tokrow[T_TOK * 2];
__device__ float g_h[(size_t)ROWS_PAD * F_DIM];
__device__ float g_eout[(size_t)ROWS_PAD * H_DIM];

typedef unsigned long long u64;

__device__ __forceinline__ u64 splat2(float a) {
    u64 r;
    asm("mov.b64 %0, {%1, %1};" : "=l"(r) : "f"(a));
    return r;
}
__device__ __forceinline__ void fma2(u64& d, u64 a, u64 b) {
    asm("fma.rn.f32x2 %0, %1, %2, %0;" : "+l"(d) : "l"(a), "l"(b));
}
__device__ __forceinline__ float2 unpack2(u64 v) {
    float2 r;
    asm("mov.b64 {%0, %1}, %2;" : "=f"(r.x), "=f"(r.y) : "l"(v));
    return r;
}

// ---------------- init ----------------
__global__ void k_init() {
    int i = blockIdx.x * blockDim.x + threadIdx.x;
    if (i < ROWS_PAD) g_rowtok[i] = -1;
    if (i < E_NUM) { g_counts[i] = 0; g_cursor[i] = 0; }
}

// ---------------- gating ----------------
__global__ void k_gate(const float* __restrict__ x, const float* __restrict__ gw,
                       const float* __restrict__ gb) {
    __shared__ float sgw[H_DIM * 17];
    int tid = threadIdx.x;
    for (int i = tid; i < H_DIM * E_NUM; i += 256) {
        int h = i >> 4, e = i & 15;
        sgw[h * 17 + e] = gw[i];
    }
    __syncthreads();
    int warp = tid >> 5, lane = tid & 31;
    int t = blockIdx.x * 8 + warp;
    float acc[E_NUM];
#pragma unroll
    for (int e = 0; e < E_NUM; e++) acc[e] = 0.f;
    const float* xr = x + (size_t)t * H_DIM;
#pragma unroll
    for (int c = 0; c < H_DIM / 32; c++) {
        int h = c * 32 + lane;
        float xv = xr[h];
#pragma unroll
        for (int e = 0; e < E_NUM; e++) acc[e] += xv * sgw[h * 17 + e];
    }
#pragma unroll
    for (int e = 0; e < E_NUM; e++) {
        float v = acc[e];
        v += __shfl_down_sync(0xffffffffu, v, 16);
        v += __shfl_down_sync(0xffffffffu, v, 8);
        v += __shfl_down_sync(0xffffffffu, v, 4);
        v += __shfl_down_sync(0xffffffffu, v, 2);
        v += __shfl_down_sync(0xffffffffu, v, 1);
        acc[e] = v;
    }
    if (lane == 0) {
        float logit[E_NUM];
#pragma unroll
        for (int e = 0; e < E_NUM; e++) logit[e] = acc[e] + gb[e];
        int i0 = 0; float m0 = logit[0];
#pragma unroll
        for (int e = 1; e < E_NUM; e++) if (logit[e] > m0) { m0 = logit[e]; i0 = e; }
        int i1 = -1; float m1 = -3.0e38f;
#pragma unroll
        for (int e = 0; e < E_NUM; e++)
            if (e != i0 && logit[e] > m1) { m1 = logit[e]; i1 = e; }
        float z = expf(m1 - m0);
        float w0 = 1.f / (1.f + z);
        float w1 = z * w0;
        g_eid[t * 2 + 0] = i0; g_eid[t * 2 + 1] = i1;
        g_gw[t * 2 + 0] = w0;  g_gw[t * 2 + 1] = w1;
        atomicAdd(&g_counts[i0], 1);
        atomicAdd(&g_counts[i1], 1);
    }
}

__global__ void k_scan() {
    if (threadIdx.x == 0) {
        int off = 0;
        g_poff[0] = 0;
        for (int e = 0; e < E_NUM; e++) {
            off += (g_counts[e] + 127) & ~127;
            g_poff[e + 1] = off;
        }
    }
}

__global__ void k_scatter() {
    int t = blockIdx.x * blockDim.x + threadIdx.x;
    if (t >= T_TOK) return;
#pragma unroll
    for (int k = 0; k < 2; k++) {
        int e = g_eid[t * 2 + k];
        int pos = atomicAdd(&g_cursor[e], 1);
        int row = g_poff[e] + pos;
        g_rowtok[row] = t;
        g_tokrow[t * 2 + k] = row;
    }
}

// ---------------- grouped GEMM: 128x128 tiles, 8x8/thread, packed f32x2 FMA ----------------
template <int KDIM, int NDIM, bool GATHER, bool RELU>
__global__ __launch_bounds__(256, 2)
void k_gemm(const float* __restrict__ Ax, const float* __restrict__ W,
            const float* __restrict__ bias) {
    int r0 = blockIdx.x * 128;
    if (r0 >= g_poff[E_NUM]) return;
    int e = 0;
#pragma unroll
    for (int i = 1; i < E_NUM; i++) if (r0 >= g_poff[i]) e = i;

    const float* Wb = W + (size_t)e * KDIM * NDIM;
    int n0 = blockIdx.y * 128;
    int tid = threadIdx.x;

    __shared__ float As[8][128];
    __shared__ float Bs[8][128];

    int arow = tid >> 1;
    int acol = (tid & 1) * 4;
    int brow = tid >> 5;
    int bcol = (tid & 31) * 4;

    const float* Aptr;
    if (GATHER) {
        int tok = g_rowtok[r0 + arow];
        Aptr = (tok >= 0) ? (Ax + (size_t)tok * KDIM) : nullptr;
    } else {
        Aptr = g_h + (size_t)(r0 + arow) * KDIM;
    }

    int ty = tid >> 4, tx = tid & 15;
    u64 acc2[8][4];
#pragma unroll
    for (int i = 0; i < 8; i++)
#pragma unroll
        for (int j = 0; j < 4; j++) acc2[i][j] = 0ull;

    for (int kk = 0; kk < KDIM; kk += 8) {
        float4 av = make_float4(0.f, 0.f, 0.f, 0.f);
        if (!GATHER || Aptr) av = *(const float4*)(Aptr + kk + acol);
        As[acol + 0][arow] = av.x;
        As[acol + 1][arow] = av.y;
        As[acol + 2][arow] = av.z;
        As[acol + 3][arow] = av.w;
        *(float4*)&Bs[brow][bcol] =
            *(const float4*)(Wb + (size_t)(kk + brow) * NDIM + n0 + bcol);
        __syncthreads();
#pragma unroll
        for (int k = 0; k < 8; k++) {
            float am[8];
            *(float4*)&am[0] = *(const float4*)&As[k][ty * 8];
            *(float4*)&am[4] = *(const float4*)&As[k][ty * 8 + 4];
            u64 bn2[4];
            {
                ulonglong2 t0 = *(const ulonglong2*)&Bs[k][tx * 8];
                ulonglong2 t1 = *(const ulonglong2*)&Bs[k][tx * 8 + 4];
                bn2[0] = t0.x; bn2[1] = t0.y; bn2[2] = t1.x; bn2[3] = t1.y;
            }
#pragma unroll
            for (int i = 0; i < 8; i++) {
                u64 a2 = splat2(am[i]);
#pragma unroll
                for (int j = 0; j < 4; j++) fma2(acc2[i][j], a2, bn2[j]);
            }
        }
        __syncthreads();
    }

    float bv[8];
#pragma unroll
    for (int j = 0; j < 8; j++) bv[j] = bias[(size_t)e * NDIM + n0 + tx * 8 + j];

    float* C = RELU ? g_h : g_eout;
#pragma unroll
    for (int i = 0; i < 8; i++) {
        int r = r0 + ty * 8 + i;
        float o[8];
#pragma unroll
        for (int j = 0; j < 4; j++) {
            float2 p = unpack2(acc2[i][j]);
            float v0 = p.x + bv[j * 2 + 0];
            float v1 = p.y + bv[j * 2 + 1];
            if (RELU) { v0 = fmaxf(v0, 0.f); v1 = fmaxf(v1, 0.f); }
            o[j * 2 + 0] = v0;
            o[j * 2 + 1] = v1;
        }
        float* cp = C + (size_t)r * NDIM + n0 + tx * 8;
        *(float4*)&cp[0] = *(float4*)&o[0];
        *(float4*)&cp[4] = *(float4*)&o[4];
    }
}

// ---------------- combine + residual + LayerNorm ----------------
__global__ void k_combine_ln(const float* __restrict__ x,
                             const float* __restrict__ gamma,
                             const float* __restrict__ beta,
                             float* __restrict__ out) {
    int warp = threadIdx.x >> 5, lane = threadIdx.x & 31;
    int t = blockIdx.x * 8 + warp;
    int row0 = g_tokrow[t * 2 + 0];
    int row1 = g_tokrow[t * 2 + 1];
    float w0 = g_gw[t * 2 + 0];
    float w1 = g_gw[t * 2 + 1];
    const float* xr = x + (size_t)t * H_DIM;
    const float* o0 = g_eout + (size_t)row0 * H_DIM;
    const float* o1 = g_eout + (size_t)row1 * H_DIM;

    float v[8];
    float s = 0.f, sq = 0.f;
#pragma unroll
    for (int j = 0; j < 8; j++) {
        int h = j * 32 + lane;
        float y = xr[h] + w0 * o0[h] + w1 * o1[h];
        v[j] = y;
        s += y;
        sq += y * y;
    }
#pragma unroll
    for (int off = 16; off > 0; off >>= 1) {
        s  += __shfl_xor_sync(0xffffffffu, s, off);
        sq += __shfl_xor_sync(0xffffffffu, sq, off);
    }
    float mu = s * (1.f / H_DIM);
    float var = sq * (1.f / H_DIM) - mu * mu;
    float rs = rsqrtf(var + 1e-5f);
    float* outr = out + (size_t)t * H_DIM;
#pragma unroll
    for (int j = 0; j < 8; j++) {
        int h = j * 32 + lane;
        outr[h] = (v[j] - mu) * rs * gamma[h] + beta[h];
    }
}

// ---------------- launch ----------------
extern "C" void kernel_launch(void* const* d_in, const int* in_sizes, int n_in,
                              void* d_out, int out_size) {
    const float* x      = (const float*)d_in[0];
    const float* gate_w = (const float*)d_in[1];
    const float* gate_b = (const float*)d_in[2];
    const float* w1     = (const float*)d_in[3];
    const float* b1     = (const float*)d_in[4];
    const float* w2     = (const float*)d_in[5];
    const float* b2     = (const float*)d_in[6];
    const float* gamma  = (const float*)d_in[7];
    const float* beta   = (const float*)d_in[8];
    float* out = (float*)d_out;

    k_init<<<(ROWS_PAD + 255) / 256, 256>>>();
    k_gate<<<T_TOK / 8, 256>>>(x, gate_w, gate_b);
    k_scan<<<1, 32>>>();
    k_scatter<<<T_TOK / 256, 256>>>();
    k_gemm<H_DIM, F_DIM, true,  true ><<<dim3(MAXT, F_DIM / 128), 256>>>(x, w1, b1);
    k_gemm<F_DIM, H_DIM, false, false><<<dim3(MAXT, H_DIM / 128), 256>>>(nullptr, w2, b2);
    k_combine_ln<<<T_TOK / 8, 256>>>(x, gamma, beta, out);
}

// round 8
// speedup vs baseline: 4.6812x; 1.0169x over previous
#include <cuda_runtime.h>
#include <cuda_fp16.h>
#include <math.h>
#include <stdint.h>

#define T_TOK   32768
#define H_DIM   256
#define F_DIM   512
#define E_NUM   16
#define ROWS_PAD 67584            // 2*T + E*128 (worst-case segment padding)
#define MAXT    (ROWS_PAD / 128)  // 528 m-tiles

// ---------------- scratch ----------------
__device__ int   g_counts[E_NUM];
__device__ int   g_cursor[E_NUM];
__device__ int   g_poff[E_NUM + 1];
__device__ int   g_eid[T_TOK * 2];
__device__ float g_gw[T_TOK * 2];
__device__ int   g_rowtok[ROWS_PAD];
__device__ int   g_tokrow[T_TOK * 2];
__device__ float g_h[(size_t)ROWS_PAD * F_DIM];
__device__ float g_eout[(size_t)ROWS_PAD * H_DIM];

// ---------------- init ----------------
__global__ void k_init() {
    int i = blockIdx.x * blockDim.x + threadIdx.x;
    if (i < ROWS_PAD) g_rowtok[i] = -1;
    if (i < E_NUM) { g_counts[i] = 0; g_cursor[i] = 0; }
}

// ---------------- gating ----------------
__global__ void k_gate(const float* __restrict__ x, const float* __restrict__ gw,
                       const float* __restrict__ gb) {
    __shared__ float sgw[H_DIM * 17];
    int tid = threadIdx.x;
    for (int i = tid; i < H_DIM * E_NUM; i += 256) {
        int h = i >> 4, e = i & 15;
        sgw[h * 17 + e] = gw[i];
    }
    __syncthreads();
    int warp = tid >> 5, lane = tid & 31;
    int t = blockIdx.x * 8 + warp;
    float acc[E_NUM];
#pragma unroll
    for (int e = 0; e < E_NUM; e++) acc[e] = 0.f;
    const float* xr = x + (size_t)t * H_DIM;
#pragma unroll
    for (int c = 0; c < H_DIM / 32; c++) {
        int h = c * 32 + lane;
        float xv = xr[h];
#pragma unroll
        for (int e = 0; e < E_NUM; e++) acc[e] += xv * sgw[h * 17 + e];
    }
#pragma unroll
    for (int e = 0; e < E_NUM; e++) {
        float v = acc[e];
        v += __shfl_down_sync(0xffffffffu, v, 16);
        v += __shfl_down_sync(0xffffffffu, v, 8);
        v += __shfl_down_sync(0xffffffffu, v, 4);
        v += __shfl_down_sync(0xffffffffu, v, 2);
        v += __shfl_down_sync(0xffffffffu, v, 1);
        acc[e] = v;
    }
    if (lane == 0) {
        float logit[E_NUM];
#pragma unroll
        for (int e = 0; e < E_NUM; e++) logit[e] = acc[e] + gb[e];
        int i0 = 0; float m0 = logit[0];
#pragma unroll
        for (int e = 1; e < E_NUM; e++) if (logit[e] > m0) { m0 = logit[e]; i0 = e; }
        int i1 = -1; float m1 = -3.0e38f;
#pragma unroll
        for (int e = 0; e < E_NUM; e++)
            if (e != i0 && logit[e] > m1) { m1 = logit[e]; i1 = e; }
        float z = expf(m1 - m0);
        float w0 = 1.f / (1.f + z);
        float w1 = z * w0;
        g_eid[t * 2 + 0] = i0; g_eid[t * 2 + 1] = i1;
        g_gw[t * 2 + 0] = w0;  g_gw[t * 2 + 1] = w1;
        atomicAdd(&g_counts[i0], 1);
        atomicAdd(&g_counts[i1], 1);
    }
}

__global__ void k_scan() {
    if (threadIdx.x == 0) {
        int off = 0;
        g_poff[0] = 0;
        for (int e = 0; e < E_NUM; e++) {
            off += (g_counts[e] + 127) & ~127;
            g_poff[e + 1] = off;
        }
    }
}

__global__ void k_scatter() {
    int t = blockIdx.x * blockDim.x + threadIdx.x;
    if (t >= T_TOK) return;
#pragma unroll
    for (int k = 0; k < 2; k++) {
        int e = g_eid[t * 2 + k];
        int pos = atomicAdd(&g_cursor[e], 1);
        int row = g_poff[e] + pos;
        g_rowtok[row] = t;
        g_tokrow[t * 2 + k] = row;
    }
}

// ---------------- grouped GEMM: R5 skeleton, fp16 tiles + HFMA2 pairs ----------------
// Thread maps, SMEM geometry, gather, and epilogue are IDENTICAL to the verified
// fp32 R5 kernel. Only the tile element type and the inner MAC changed.
template <int KDIM, int NDIM, bool GATHER, bool RELU>
__global__ __launch_bounds__(256, 2)
void k_gemm(const float* __restrict__ Ax, const float* __restrict__ W,
            const float* __restrict__ bias) {
    int r0 = blockIdx.x * 128;
    if (r0 >= g_poff[E_NUM]) return;
    int e = 0;
#pragma unroll
    for (int i = 1; i < E_NUM; i++) if (r0 >= g_poff[i]) e = i;

    const float* Wb = W + (size_t)e * KDIM * NDIM;
    int n0 = blockIdx.y * 128;
    int tid = threadIdx.x;

    __shared__ __half As[8][128];
    __shared__ __half Bs[8][128];

    int arow = tid >> 1;
    int acol = (tid & 1) * 4;
    int brow = tid >> 5;
    int bcol = (tid & 31) * 4;

    const float* Aptr;
    if (GATHER) {
        int tok = g_rowtok[r0 + arow];
        Aptr = (tok >= 0) ? (Ax + (size_t)tok * KDIM) : nullptr;
    } else {
        Aptr = g_h + (size_t)(r0 + arow) * KDIM;
    }

    int ty = tid >> 4, tx = tid & 15;
    float accf[8][8];
#pragma unroll
    for (int i = 0; i < 8; i++)
#pragma unroll
        for (int j = 0; j < 8; j++) accf[i][j] = 0.f;

    for (int kk = 0; kk < KDIM; kk += 8) {
        float4 av = make_float4(0.f, 0.f, 0.f, 0.f);
        if (!GATHER || Aptr) av = *(const float4*)(Aptr + kk + acol);
        As[acol + 0][arow] = __float2half(av.x);
        As[acol + 1][arow] = __float2half(av.y);
        As[acol + 2][arow] = __float2half(av.z);
        As[acol + 3][arow] = __float2half(av.w);
        {
            float4 bw = *(const float4*)(Wb + (size_t)(kk + brow) * NDIM + n0 + bcol);
            __half2 p0 = __floats2half2_rn(bw.x, bw.y);
            __half2 p1 = __floats2half2_rn(bw.z, bw.w);
            uint2 pk;
            pk.x = reinterpret_cast<uint32_t&>(p0);
            pk.y = reinterpret_cast<uint32_t&>(p1);
            *(uint2*)&Bs[brow][bcol] = pk;
        }
        __syncthreads();

        __half2 acc2[8][4];
#pragma unroll
        for (int i = 0; i < 8; i++)
#pragma unroll
            for (int j = 0; j < 4; j++) acc2[i][j] = __float2half2_rn(0.f);

#pragma unroll
        for (int k = 0; k < 8; k++) {
            uint4 ap = *(const uint4*)&As[k][ty * 8];
            __half2 a2[8];
            {
                __half2 q0 = reinterpret_cast<__half2&>(ap.x);
                __half2 q1 = reinterpret_cast<__half2&>(ap.y);
                __half2 q2 = reinterpret_cast<__half2&>(ap.z);
                __half2 q3 = reinterpret_cast<__half2&>(ap.w);
                a2[0] = __low2half2(q0);  a2[1] = __high2half2(q0);
                a2[2] = __low2half2(q1);  a2[3] = __high2half2(q1);
                a2[4] = __low2half2(q2);  a2[5] = __high2half2(q2);
                a2[6] = __low2half2(q3);  a2[7] = __high2half2(q3);
            }
            uint4 bp = *(const uint4*)&Bs[k][tx * 8];
            __half2 b2[4];
            b2[0] = reinterpret_cast<__half2&>(bp.x);
            b2[1] = reinterpret_cast<__half2&>(bp.y);
            b2[2] = reinterpret_cast<__half2&>(bp.z);
            b2[3] = reinterpret_cast<__half2&>(bp.w);
#pragma unroll
            for (int i = 0; i < 8; i++)
#pragma unroll
                for (int j = 0; j < 4; j++)
                    acc2[i][j] = __hfma2(a2[i], b2[j], acc2[i][j]);
        }
        // flush fp16 window into fp32 accumulators
#pragma unroll
        for (int i = 0; i < 8; i++)
#pragma unroll
            for (int j = 0; j < 4; j++) {
                float2 f = __half22float2(acc2[i][j]);
                accf[i][j * 2 + 0] += f.x;
                accf[i][j * 2 + 1] += f.y;
            }
        __syncthreads();
    }

    float bv[8];
#pragma unroll
    for (int j = 0; j < 8; j++) bv[j] = bias[(size_t)e * NDIM + n0 + tx * 8 + j];

    float* C = RELU ? g_h : g_eout;
#pragma unroll
    for (int i = 0; i < 8; i++) {
        int r = r0 + ty * 8 + i;
        float o[8];
#pragma unroll
        for (int j = 0; j < 8; j++) {
            float v = accf[i][j] + bv[j];
            if (RELU) v = fmaxf(v, 0.f);
            o[j] = v;
        }
        float* cp = C + (size_t)r * NDIM + n0 + tx * 8;
        *(float4*)&cp[0] = *(float4*)&o[0];
        *(float4*)&cp[4] = *(float4*)&o[4];
    }
}

// ---------------- combine + residual + LayerNorm ----------------
__global__ void k_combine_ln(const float* __restrict__ x,
                             const float* __restrict__ gamma,
                             const float* __restrict__ beta,
                             float* __restrict__ out) {
    int warp = threadIdx.x >> 5, lane = threadIdx.x & 31;
    int t = blockIdx.x * 8 + warp;
    int row0 = g_tokrow[t * 2 + 0];
    int row1 = g_tokrow[t * 2 + 1];
    float w0 = g_gw[t * 2 + 0];
    float w1 = g_gw[t * 2 + 1];
    const float* xr = x + (size_t)t * H_DIM;
    const float* o0 = g_eout + (size_t)row0 * H_DIM;
    const float* o1 = g_eout + (size_t)row1 * H_DIM;

    float v[8];
    float s = 0.f, sq = 0.f;
#pragma unroll
    for (int j = 0; j < 8; j++) {
        int h = j * 32 + lane;
        float y = xr[h] + w0 * o0[h] + w1 * o1[h];
        v[j] = y;
        s += y;
        sq += y * y;
    }
#pragma unroll
    for (int off = 16; off > 0; off >>= 1) {
        s  += __shfl_xor_sync(0xffffffffu, s, off);
        sq += __shfl_xor_sync(0xffffffffu, sq, off);
    }
    float mu = s * (1.f / H_DIM);
    float var = sq * (1.f / H_DIM) - mu * mu;
    float rs = rsqrtf(var + 1e-5f);
    float* outr = out + (size_t)t * H_DIM;
#pragma unroll
    for (int j = 0; j < 8; j++) {
        int h = j * 32 + lane;
        outr[h] = (v[j] - mu) * rs * gamma[h] + beta[h];
    }
}

// ---------------- launch ----------------
extern "C" void kernel_launch(void* const* d_in, const int* in_sizes, int n_in,
                              void* d_out, int out_size) {
    const float* x      = (const float*)d_in[0];
    const float* gate_w = (const float*)d_in[1];
    const float* gate_b = (const float*)d_in[2];
    const float* w1     = (const float*)d_in[3];
    const float* b1     = (const float*)d_in[4];
    const float* w2     = (const float*)d_in[5];
    const float* b2     = (const float*)d_in[6];
    const float* gamma  = (const float*)d_in[7];
    const float* beta   = (const float*)d_in[8];
    float* out = (float*)d_out;

    k_init<<<(ROWS_PAD + 255) / 256, 256>>>();
    k_gate<<<T_TOK / 8, 256>>>(x, gate_w, gate_b);
    k_scan<<<1, 32>>>();
    k_scatter<<<T_TOK / 256, 256>>>();
    k_gemm<H_DIM, F_DIM, true,  true ><<<dim3(MAXT, F_DIM / 128), 256>>>(x, w1, b1);
    k_gemm<F_DIM, H_DIM, false, false><<<dim3(MAXT, H_DIM / 128), 256>>>(nullptr, w2, b2);
    k_combine_ln<<<T_TOK / 8, 256>>>(x, gamma, beta, out);
}

// round 9
// speedup vs baseline: 5.3214x; 1.1368x over previous
#include <cuda_runtime.h>
#include <cuda_fp16.h>
#include <math.h>
#include <stdint.h>

#define T_TOK   32768
#define H_DIM   256
#define F_DIM   512
#define E_NUM   16
#define ROWS_PAD 67584            // 2*T + E*128 (worst-case segment padding)
#define MAXT    (ROWS_PAD / 128)  // 528 m-tiles

// ---------------- scratch ----------------
__device__ int   g_counts[E_NUM];
__device__ int   g_cursor[E_NUM];
__device__ int   g_poff[E_NUM + 1];
__device__ int   g_eid[T_TOK * 2];
__device__ float g_gw[T_TOK * 2];
__device__ int   g_rowtok[ROWS_PAD];
__device__ int   g_tokrow[T_TOK * 2];
__device__ float g_h[(size_t)ROWS_PAD * F_DIM];
__device__ float g_eout[(size_t)ROWS_PAD * H_DIM];

// ---------------- init ----------------
__global__ void k_init() {
    int i = blockIdx.x * blockDim.x + threadIdx.x;
    if (i < ROWS_PAD) g_rowtok[i] = -1;
    if (i < E_NUM) { g_counts[i] = 0; g_cursor[i] = 0; }
}

// ---------------- gating ----------------
__global__ void k_gate(const float* __restrict__ x, const float* __restrict__ gw,
                       const float* __restrict__ gb) {
    __shared__ float sgw[H_DIM * 17];
    int tid = threadIdx.x;
    for (int i = tid; i < H_DIM * E_NUM; i += 256) {
        int h = i >> 4, e = i & 15;
        sgw[h * 17 + e] = gw[i];
    }
    __syncthreads();
    int warp = tid >> 5, lane = tid & 31;
    int t = blockIdx.x * 8 + warp;
    float acc[E_NUM];
#pragma unroll
    for (int e = 0; e < E_NUM; e++) acc[e] = 0.f;
    const float* xr = x + (size_t)t * H_DIM;
#pragma unroll
    for (int c = 0; c < H_DIM / 32; c++) {
        int h = c * 32 + lane;
        float xv = xr[h];
#pragma unroll
        for (int e = 0; e < E_NUM; e++) acc[e] += xv * sgw[h * 17 + e];
    }
#pragma unroll
    for (int e = 0; e < E_NUM; e++) {
        float v = acc[e];
        v += __shfl_down_sync(0xffffffffu, v, 16);
        v += __shfl_down_sync(0xffffffffu, v, 8);
        v += __shfl_down_sync(0xffffffffu, v, 4);
        v += __shfl_down_sync(0xffffffffu, v, 2);
        v += __shfl_down_sync(0xffffffffu, v, 1);
        acc[e] = v;
    }
    if (lane == 0) {
        float logit[E_NUM];
#pragma unroll
        for (int e = 0; e < E_NUM; e++) logit[e] = acc[e] + gb[e];
        int i0 = 0; float m0 = logit[0];
#pragma unroll
        for (int e = 1; e < E_NUM; e++) if (logit[e] > m0) { m0 = logit[e]; i0 = e; }
        int i1 = -1; float m1 = -3.0e38f;
#pragma unroll
        for (int e = 0; e < E_NUM; e++)
            if (e != i0 && logit[e] > m1) { m1 = logit[e]; i1 = e; }
        float z = expf(m1 - m0);
        float w0 = 1.f / (1.f + z);
        float w1 = z * w0;
        g_eid[t * 2 + 0] = i0; g_eid[t * 2 + 1] = i1;
        g_gw[t * 2 + 0] = w0;  g_gw[t * 2 + 1] = w1;
        atomicAdd(&g_counts[i0], 1);
        atomicAdd(&g_counts[i1], 1);
    }
}

__global__ void k_scan() {
    if (threadIdx.x == 0) {
        int off = 0;
        g_poff[0] = 0;
        for (int e = 0; e < E_NUM; e++) {
            off += (g_counts[e] + 127) & ~127;
            g_poff[e + 1] = off;
        }
    }
}

__global__ void k_scatter() {
    int t = blockIdx.x * blockDim.x + threadIdx.x;
    if (t >= T_TOK) return;
#pragma unroll
    for (int k = 0; k < 2; k++) {
        int e = g_eid[t * 2 + k];
        int pos = atomicAdd(&g_cursor[e], 1);
        int row = g_poff[e] + pos;
        g_rowtok[row] = t;
        g_tokrow[t * 2 + k] = row;
    }
}

// ---------------- grouped GEMM: fp16 HFMA2, pre-splatted A, lazy flush ----------------
// Same verified thread maps / geometry as R5/R8. A tile stored as splatted half2
// (both lanes equal) so the inner loop has zero unpack ops. fp16 accumulators
// flushed to fp32 every 4 chunks (32 k-steps).
template <int KDIM, int NDIM, bool GATHER, bool RELU>
__global__ __launch_bounds__(256, 2)
void k_gemm(const float* __restrict__ Ax, const float* __restrict__ W,
            const float* __restrict__ bias) {
    int r0 = blockIdx.x * 128;
    if (r0 >= g_poff[E_NUM]) return;
    int e = 0;
#pragma unroll
    for (int i = 1; i < E_NUM; i++) if (r0 >= g_poff[i]) e = i;

    const float* Wb = W + (size_t)e * KDIM * NDIM;
    int n0 = blockIdx.y * 128;
    int tid = threadIdx.x;

    __shared__ __half2 As2[8][128];   // splatted: both lanes = a value
    __shared__ __half  Bs[8][128];

    int arow = tid >> 1;
    int acol = (tid & 1) * 4;
    int brow = tid >> 5;
    int bcol = (tid & 31) * 4;

    const float* Aptr;
    if (GATHER) {
        int tok = g_rowtok[r0 + arow];
        Aptr = (tok >= 0) ? (Ax + (size_t)tok * KDIM) : nullptr;
    } else {
        Aptr = g_h + (size_t)(r0 + arow) * KDIM;
    }

    int ty = tid >> 4, tx = tid & 15;
    float accf[8][8];
#pragma unroll
    for (int i = 0; i < 8; i++)
#pragma unroll
        for (int j = 0; j < 8; j++) accf[i][j] = 0.f;

    __half2 acc2[8][4];
#pragma unroll
    for (int i = 0; i < 8; i++)
#pragma unroll
        for (int j = 0; j < 4; j++) acc2[i][j] = __float2half2_rn(0.f);

    constexpr int CHUNKS = KDIM / 8;
    for (int c = 0; c < CHUNKS; c++) {
        int kk = c * 8;
        float4 av = make_float4(0.f, 0.f, 0.f, 0.f);
        if (!GATHER || Aptr) av = *(const float4*)(Aptr + kk + acol);
        As2[acol + 0][arow] = __float2half2_rn(av.x);
        As2[acol + 1][arow] = __float2half2_rn(av.y);
        As2[acol + 2][arow] = __float2half2_rn(av.z);
        As2[acol + 3][arow] = __float2half2_rn(av.w);
        {
            float4 bw = *(const float4*)(Wb + (size_t)(kk + brow) * NDIM + n0 + bcol);
            __half2 p0 = __floats2half2_rn(bw.x, bw.y);
            __half2 p1 = __floats2half2_rn(bw.z, bw.w);
            uint2 pk;
            pk.x = reinterpret_cast<uint32_t&>(p0);
            pk.y = reinterpret_cast<uint32_t&>(p1);
            *(uint2*)&Bs[brow][bcol] = pk;
        }
        __syncthreads();

#pragma unroll
        for (int k = 0; k < 8; k++) {
            __half2 a2[8];
            *(uint4*)&a2[0] = *(const uint4*)&As2[k][ty * 8];
            *(uint4*)&a2[4] = *(const uint4*)&As2[k][ty * 8 + 4];
            __half2 b2[4];
            {
                uint4 bp = *(const uint4*)&Bs[k][tx * 8];
                b2[0] = reinterpret_cast<__half2&>(bp.x);
                b2[1] = reinterpret_cast<__half2&>(bp.y);
                b2[2] = reinterpret_cast<__half2&>(bp.z);
                b2[3] = reinterpret_cast<__half2&>(bp.w);
            }
#pragma unroll
            for (int i = 0; i < 8; i++)
#pragma unroll
                for (int j = 0; j < 4; j++)
                    acc2[i][j] = __hfma2(a2[i], b2[j], acc2[i][j]);
        }

        if ((c & 3) == 3) {   // flush fp16 window -> fp32 every 32 k-steps
#pragma unroll
            for (int i = 0; i < 8; i++)
#pragma unroll
                for (int j = 0; j < 4; j++) {
                    float2 f = __half22float2(acc2[i][j]);
                    accf[i][j * 2 + 0] += f.x;
                    accf[i][j * 2 + 1] += f.y;
                    acc2[i][j] = __float2half2_rn(0.f);
                }
        }
        __syncthreads();
    }

    float bv[8];
#pragma unroll
    for (int j = 0; j < 8; j++) bv[j] = bias[(size_t)e * NDIM + n0 + tx * 8 + j];

    float* C = RELU ? g_h : g_eout;
#pragma unroll
    for (int i = 0; i < 8; i++) {
        int r = r0 + ty * 8 + i;
        float o[8];
#pragma unroll
        for (int j = 0; j < 8; j++) {
            float v = accf[i][j] + bv[j];
            if (RELU) v = fmaxf(v, 0.f);
            o[j] = v;
        }
        float* cp = C + (size_t)r * NDIM + n0 + tx * 8;
        *(float4*)&cp[0] = *(float4*)&o[0];
        *(float4*)&cp[4] = *(float4*)&o[4];
    }
}

// ---------------- combine + residual + LayerNorm ----------------
__global__ void k_combine_ln(const float* __restrict__ x,
                             const float* __restrict__ gamma,
                             const float* __restrict__ beta,
                             float* __restrict__ out) {
    int warp = threadIdx.x >> 5, lane = threadIdx.x & 31;
    int t = blockIdx.x * 8 + warp;
    int row0 = g_tokrow[t * 2 + 0];
    int row1 = g_tokrow[t * 2 + 1];
    float w0 = g_gw[t * 2 + 0];
    float w1 = g_gw[t * 2 + 1];
    const float* xr = x + (size_t)t * H_DIM;
    const float* o0 = g_eout + (size_t)row0 * H_DIM;
    const float* o1 = g_eout + (size_t)row1 * H_DIM;

    float v[8];
    float s = 0.f, sq = 0.f;
#pragma unroll
    for (int j = 0; j < 8; j++) {
        int h = j * 32 + lane;
        float y = xr[h] + w0 * o0[h] + w1 * o1[h];
        v[j] = y;
        s += y;
        sq += y * y;
    }
#pragma unroll
    for (int off = 16; off > 0; off >>= 1) {
        s  += __shfl_xor_sync(0xffffffffu, s, off);
        sq += __shfl_xor_sync(0xffffffffu, sq, off);
    }
    float mu = s * (1.f / H_DIM);
    float var = sq * (1.f / H_DIM) - mu * mu;
    float rs = rsqrtf(var + 1e-5f);
    float* outr = out + (size_t)t * H_DIM;
#pragma unroll
    for (int j = 0; j < 8; j++) {
        int h = j * 32 + lane;
        outr[h] = (v[j] - mu) * rs * gamma[h] + beta[h];
    }
}

// ---------------- launch ----------------
extern "C" void kernel_launch(void* const* d_in, const int* in_sizes, int n_in,
                              void* d_out, int out_size) {
    const float* x      = (const float*)d_in[0];
    const float* gate_w = (const float*)d_in[1];
    const float* gate_b = (const float*)d_in[2];
    const float* w1     = (const float*)d_in[3];
    const float* b1     = (const float*)d_in[4];
    const float* w2     = (const float*)d_in[5];
    const float* b2     = (const float*)d_in[6];
    const float* gamma  = (const float*)d_in[7];
    const float* beta   = (const float*)d_in[8];
    float* out = (float*)d_out;

    k_init<<<(ROWS_PAD + 255) / 256, 256>>>();
    k_gate<<<T_TOK / 8, 256>>>(x, gate_w, gate_b);
    k_scan<<<1, 32>>>();
    k_scatter<<<T_TOK / 256, 256>>>();
    k_gemm<H_DIM, F_DIM, true,  true ><<<dim3(MAXT, F_DIM / 128), 256>>>(x, w1, b1);
    k_gemm<F_DIM, H_DIM, false, false><<<dim3(MAXT, H_DIM / 128), 256>>>(nullptr, w2, b2);
    k_combine_ln<<<T_TOK / 8, 256>>>(x, gamma, beta, out);
}

// round 11
// speedup vs baseline: 5.9666x; 1.1212x over previous
#include <cuda_runtime.h>
#include <cuda_fp16.h>
#include <math.h>
#include <stdint.h>

#define T_TOK   32768
#define H_DIM   256
#define F_DIM   512
#define E_NUM   16
#define ROWS_PAD 67584            // 2*T + E*128 (worst-case segment padding)
#define MAXT    (ROWS_PAD / 128)  // 528 m-tiles

// ---------------- scratch (ALL accessed via device symbols ONLY) ----------------
__device__ int    g_counts[E_NUM];
__device__ int    g_cursor[E_NUM];
__device__ int    g_poff[E_NUM + 1];
__device__ int    g_eid[T_TOK * 2];
__device__ float  g_gw[T_TOK * 2];
__device__ int    g_rowtok[ROWS_PAD];
__device__ int    g_tokrow[T_TOK * 2];
__device__ __half g_xh[(size_t)T_TOK * H_DIM];            // x (fp16)
__device__ __half g_h[(size_t)ROWS_PAD * F_DIM];          // hidden (fp16)
__device__ float  g_eout[(size_t)ROWS_PAD * H_DIM];       // expert out (fp32)
__device__ __half g_w1h[(size_t)E_NUM * H_DIM * F_DIM];   // [E][K=H][N=F] fp16
__device__ __half g_w2h[(size_t)E_NUM * F_DIM * H_DIM];   // [E][K=F][N=H] fp16

// ---------------- init ----------------
__global__ void k_init() {
    int i = blockIdx.x * blockDim.x + threadIdx.x;
    if (i < ROWS_PAD) g_rowtok[i] = -1;
    if (i < E_NUM) { g_counts[i] = 0; g_cursor[i] = 0; }
}

// ---------------- fp32 -> fp16 converters (dst = device symbol, in device code) ----------------
__device__ __forceinline__ uint4 cvt8(const float* __restrict__ src, int i) {
    const float4* s = (const float4*)src + i * 2;
    float4 u0 = s[0], u1 = s[1];
    __half2 h0 = __floats2half2_rn(u0.x, u0.y);
    __half2 h1 = __floats2half2_rn(u0.z, u0.w);
    __half2 h2 = __floats2half2_rn(u1.x, u1.y);
    __half2 h3 = __floats2half2_rn(u1.z, u1.w);
    uint4 o;
    o.x = reinterpret_cast<uint32_t&>(h0);
    o.y = reinterpret_cast<uint32_t&>(h1);
    o.z = reinterpret_cast<uint32_t&>(h2);
    o.w = reinterpret_cast<uint32_t&>(h3);
    return o;
}
__global__ void k_cvt_x(const float* __restrict__ src) {
    int i = blockIdx.x * blockDim.x + threadIdx.x;
    ((uint4*)g_xh)[i] = cvt8(src, i);
}
__global__ void k_cvt_w1(const float* __restrict__ src) {
    int i = blockIdx.x * blockDim.x + threadIdx.x;
    ((uint4*)g_w1h)[i] = cvt8(src, i);
}
__global__ void k_cvt_w2(const float* __restrict__ src) {
    int i = blockIdx.x * blockDim.x + threadIdx.x;
    ((uint4*)g_w2h)[i] = cvt8(src, i);
}

// ---------------- gating ----------------
__global__ void k_gate(const float* __restrict__ x, const float* __restrict__ gw,
                       const float* __restrict__ gb) {
    __shared__ float sgw[H_DIM * 17];
    int tid = threadIdx.x;
    for (int i = tid; i < H_DIM * E_NUM; i += 256) {
        int h = i >> 4, e = i & 15;
        sgw[h * 17 + e] = gw[i];
    }
    __syncthreads();
    int warp = tid >> 5, lane = tid & 31;
    int t = blockIdx.x * 8 + warp;
    float acc[E_NUM];
#pragma unroll
    for (int e = 0; e < E_NUM; e++) acc[e] = 0.f;
    const float* xr = x + (size_t)t * H_DIM;
#pragma unroll
    for (int c = 0; c < H_DIM / 32; c++) {
        int h = c * 32 + lane;
        float xv = xr[h];
#pragma unroll
        for (int e = 0; e < E_NUM; e++) acc[e] += xv * sgw[h * 17 + e];
    }
#pragma unroll
    for (int e = 0; e < E_NUM; e++) {
        float v = acc[e];
        v += __shfl_down_sync(0xffffffffu, v, 16);
        v += __shfl_down_sync(0xffffffffu, v, 8);
        v += __shfl_down_sync(0xffffffffu, v, 4);
        v += __shfl_down_sync(0xffffffffu, v, 2);
        v += __shfl_down_sync(0xffffffffu, v, 1);
        acc[e] = v;
    }
    if (lane == 0) {
        float logit[E_NUM];
#pragma unroll
        for (int e = 0; e < E_NUM; e++) logit[e] = acc[e] + gb[e];
        int i0 = 0; float m0 = logit[0];
#pragma unroll
        for (int e = 1; e < E_NUM; e++) if (logit[e] > m0) { m0 = logit[e]; i0 = e; }
        int i1 = -1; float m1 = -3.0e38f;
#pragma unroll
        for (int e = 0; e < E_NUM; e++)
            if (e != i0 && logit[e] > m1) { m1 = logit[e]; i1 = e; }
        float z = expf(m1 - m0);
        float w0 = 1.f / (1.f + z);
        float w1 = z * w0;
        g_eid[t * 2 + 0] = i0; g_eid[t * 2 + 1] = i1;
        g_gw[t * 2 + 0] = w0;  g_gw[t * 2 + 1] = w1;
        atomicAdd(&g_counts[i0], 1);
        atomicAdd(&g_counts[i1], 1);
    }
}

__global__ void k_scan() {
    if (threadIdx.x == 0) {
        int off = 0;
        g_poff[0] = 0;
        for (int e = 0; e < E_NUM; e++) {
            off += (g_counts[e] + 127) & ~127;
            g_poff[e + 1] = off;
        }
    }
}

__global__ void k_scatter() {
    int t = blockIdx.x * blockDim.x + threadIdx.x;
    if (t >= T_TOK) return;
#pragma unroll
    for (int k = 0; k < 2; k++) {
        int e = g_eid[t * 2 + k];
        int pos = atomicAdd(&g_cursor[e], 1);
        int row = g_poff[e] + pos;
        g_rowtok[row] = t;
        g_tokrow[t * 2 + k] = row;
    }
}

// ---------------- grouped GEMM: all-fp16, HFMA2, double-buffered, lazy flush ----------------
// Verified R5/R8 thread maps. A from g_xh (gather) or g_h; W from g_w1h/g_w2h (symbols).
template <int KDIM, int NDIM, bool GATHER, bool RELU>
__global__ __launch_bounds__(256, 2)
void k_gemm(const float* __restrict__ bias) {
    int r0 = blockIdx.x * 128;
    if (r0 >= g_poff[E_NUM]) return;
    int e = 0;
#pragma unroll
    for (int i = 1; i < E_NUM; i++) if (r0 >= g_poff[i]) e = i;

    const __half* Wb = (GATHER ? g_w1h : g_w2h) + (size_t)e * KDIM * NDIM;
    int n0 = blockIdx.y * 128;
    int tid = threadIdx.x;

    __shared__ __half As[2][8][128];
    __shared__ __half Bs[2][8][128];

    int arow = tid >> 1;
    int acol = (tid & 1) * 4;
    int brow = tid >> 5;
    int bcol = (tid & 31) * 4;

    const __half* Aptr;
    if (GATHER) {
        int tok = g_rowtok[r0 + arow];
        Aptr = (tok >= 0) ? (g_xh + (size_t)tok * KDIM + acol) : nullptr;
    } else {
        Aptr = g_h + (size_t)(r0 + arow) * KDIM + acol;
    }
    const __half* Wrow = Wb + (size_t)brow * NDIM + n0 + bcol;

    int ty = tid >> 4, tx = tid & 15;
    float accf[8][8];
#pragma unroll
    for (int i = 0; i < 8; i++)
#pragma unroll
        for (int j = 0; j < 8; j++) accf[i][j] = 0.f;

    __half2 acc2[8][4];
#pragma unroll
    for (int i = 0; i < 8; i++)
#pragma unroll
        for (int j = 0; j < 4; j++) acc2[i][j] = __float2half2_rn(0.f);

    constexpr int CHUNKS = KDIM / 8;

    // prologue: chunk 0 into buffer 0
    {
        uint2 avr = make_uint2(0u, 0u);
        if (!GATHER || Aptr) avr = *(const uint2*)(Aptr);
        const __half* hv = (const __half*)&avr;
        As[0][acol + 0][arow] = hv[0];
        As[0][acol + 1][arow] = hv[1];
        As[0][acol + 2][arow] = hv[2];
        As[0][acol + 3][arow] = hv[3];
        *(uint2*)&Bs[0][brow][bcol] = *(const uint2*)(Wrow);
    }
    __syncthreads();

    for (int c = 0; c < CHUNKS; c++) {
        const int b = c & 1;
        uint2 avr, bwr;
        const bool more = (c + 1 < CHUNKS);
        if (more) {
            avr = make_uint2(0u, 0u);
            if (!GATHER || Aptr) avr = *(const uint2*)(Aptr + (c + 1) * 8);
            bwr = *(const uint2*)(Wrow + (size_t)(c + 1) * 8 * NDIM);
        }

#pragma unroll
        for (int k = 0; k < 8; k++) {
            __half2 a2[8];
            {
                uint4 ap = *(const uint4*)&As[b][k][ty * 8];
                __half2 q0 = reinterpret_cast<__half2&>(ap.x);
                __half2 q1 = reinterpret_cast<__half2&>(ap.y);
                __half2 q2 = reinterpret_cast<__half2&>(ap.z);
                __half2 q3 = reinterpret_cast<__half2&>(ap.w);
                a2[0] = __low2half2(q0);  a2[1] = __high2half2(q0);
                a2[2] = __low2half2(q1);  a2[3] = __high2half2(q1);
                a2[4] = __low2half2(q2);  a2[5] = __high2half2(q2);
                a2[6] = __low2half2(q3);  a2[7] = __high2half2(q3);
            }
            __half2 b2[4];
            {
                uint4 bp = *(const uint4*)&Bs[b][k][tx * 8];
                b2[0] = reinterpret_cast<__half2&>(bp.x);
                b2[1] = reinterpret_cast<__half2&>(bp.y);
                b2[2] = reinterpret_cast<__half2&>(bp.z);
                b2[3] = reinterpret_cast<__half2&>(bp.w);
            }
#pragma unroll
            for (int i = 0; i < 8; i++)
#pragma unroll
                for (int j = 0; j < 4; j++)
                    acc2[i][j] = __hfma2(a2[i], b2[j], acc2[i][j]);
        }

        if ((c & 3) == 3) {   // flush fp16 window -> fp32 every 32 k-steps
#pragma unroll
            for (int i = 0; i < 8; i++)
#pragma unroll
                for (int j = 0; j < 4; j++) {
                    float2 f = __half22float2(acc2[i][j]);
                    accf[i][j * 2 + 0] += f.x;
                    accf[i][j * 2 + 1] += f.y;
                    acc2[i][j] = __float2half2_rn(0.f);
                }
        }

        if (more) {
            const int nb = 1 - b;
            const __half* hv = (const __half*)&avr;
            As[nb][acol + 0][arow] = hv[0];
            As[nb][acol + 1][arow] = hv[1];
            As[nb][acol + 2][arow] = hv[2];
            As[nb][acol + 3][arow] = hv[3];
            *(uint2*)&Bs[nb][brow][bcol] = bwr;
            __syncthreads();
        }
    }

    float bv[8];
#pragma unroll
    for (int j = 0; j < 8; j++) bv[j] = bias[(size_t)e * NDIM + n0 + tx * 8 + j];

#pragma unroll
    for (int i = 0; i < 8; i++) {
        int r = r0 + ty * 8 + i;
        float o[8];
#pragma unroll
        for (int j = 0; j < 8; j++) {
            float v = accf[i][j] + bv[j];
            if (RELU) v = fmaxf(v, 0.f);
            o[j] = v;
        }
        if (RELU) {
            __half2 h0 = __floats2half2_rn(o[0], o[1]);
            __half2 h1 = __floats2half2_rn(o[2], o[3]);
            __half2 h2 = __floats2half2_rn(o[4], o[5]);
            __half2 h3 = __floats2half2_rn(o[6], o[7]);
            uint4 pk;
            pk.x = reinterpret_cast<uint32_t&>(h0);
            pk.y = reinterpret_cast<uint32_t&>(h1);
            pk.z = reinterpret_cast<uint32_t&>(h2);
            pk.w = reinterpret_cast<uint32_t&>(h3);
            *(uint4*)(g_h + (size_t)r * NDIM + n0 + tx * 8) = pk;
        } else {
            float* cp = g_eout + (size_t)r * NDIM + n0 + tx * 8;
            *(float4*)&cp[0] = *(float4*)&o[0];
            *(float4*)&cp[4] = *(float4*)&o[4];
        }
    }
}

// ---------------- combine + residual + LayerNorm ----------------
__global__ void k_combine_ln(const float* __restrict__ x,
                             const float* __restrict__ gamma,
                             const float* __restrict__ beta,
                             float* __restrict__ out) {
    int warp = threadIdx.x >> 5, lane = threadIdx.x & 31;
    int t = blockIdx.x * 8 + warp;
    int row0 = g_tokrow[t * 2 + 0];
    int row1 = g_tokrow[t * 2 + 1];
    float w0 = g_gw[t * 2 + 0];
    float w1 = g_gw[t * 2 + 1];
    const float* xr = x + (size_t)t * H_DIM;
    const float* o0 = g_eout + (size_t)row0 * H_DIM;
    const float* o1 = g_eout + (size_t)row1 * H_DIM;

    float v[8];
    float s = 0.f, sq = 0.f;
#pragma unroll
    for (int j = 0; j < 8; j++) {
        int h = j * 32 + lane;
        float y = xr[h] + w0 * o0[h] + w1 * o1[h];
        v[j] = y;
        s += y;
        sq += y * y;
    }
#pragma unroll
    for (int off = 16; off > 0; off >>= 1) {
        s  += __shfl_xor_sync(0xffffffffu, s, off);
        sq += __shfl_xor_sync(0xffffffffu, sq, off);
    }
    float mu = s * (1.f / H_DIM);
    float var = sq * (1.f / H_DIM) - mu * mu;
    float rs = rsqrtf(var + 1e-5f);
    float* outr = out + (size_t)t * H_DIM;
#pragma unroll
    for (int j = 0; j < 8; j++) {
        int h = j * 32 + lane;
        outr[h] = (v[j] - mu) * rs * gamma[h] + beta[h];
    }
}

// ---------------- launch ----------------
extern "C" void kernel_launch(void* const* d_in, const int* in_sizes, int n_in,
                              void* d_out, int out_size) {
    const float* x      = (const float*)d_in[0];
    const float* gate_w = (const float*)d_in[1];
    const float* gate_b = (const float*)d_in[2];
    const float* w1     = (const float*)d_in[3];
    const float* b1     = (const float*)d_in[4];
    const float* w2     = (const float*)d_in[5];
    const float* b2     = (const float*)d_in[6];
    const float* gamma  = (const float*)d_in[7];
    const float* beta   = (const float*)d_in[8];
    float* out = (float*)d_out;

    k_init<<<(ROWS_PAD + 255) / 256, 256>>>();
    k_cvt_x <<<T_TOK * H_DIM / 8 / 256, 256>>>(x);
    k_cvt_w1<<<E_NUM * H_DIM * F_DIM / 8 / 256, 256>>>(w1);
    k_cvt_w2<<<E_NUM * F_DIM * H_DIM / 8 / 256, 256>>>(w2);
    k_gate<<<T_TOK / 8, 256>>>(x, gate_w, gate_b);
    k_scan<<<1, 32>>>();
    k_scatter<<<T_TOK / 256, 256>>>();
    k_gemm<H_DIM, F_DIM, true,  true ><<<dim3(MAXT, F_DIM / 128), 256>>>(b1);
    k_gemm<F_DIM, H_DIM, false, false><<<dim3(MAXT, H_DIM / 128), 256>>>(b2);
    k_combine_ln<<<T_TOK / 8, 256>>>(x, gamma, beta, out);
}

// round 12
// speedup vs baseline: 6.2354x; 1.0451x over previous
#include <cuda_runtime.h>
#include <cuda_fp16.h>
#include <math.h>
#include <stdint.h>

#define T_TOK   32768
#define H_DIM   256
#define F_DIM   512
#define E_NUM   16
#define ROWS_PAD 67584            // 2*T + E*128 (worst-case segment padding)
#define MAXT    (ROWS_PAD / 128)  // 528 m-tiles

// ---------------- scratch (ALL accessed via device symbols ONLY) ----------------
__device__ int    g_counts[E_NUM];
__device__ int    g_cursor[E_NUM];
__device__ int    g_poff[E_NUM + 1];
__device__ int    g_eid[T_TOK * 2];
__device__ float  g_gw[T_TOK * 2];
__device__ int    g_rowtok[ROWS_PAD];
__device__ int    g_tokrow[T_TOK * 2];
__device__ __half g_xh[(size_t)T_TOK * H_DIM];            // x (fp16)
__device__ __half g_h[(size_t)ROWS_PAD * F_DIM];          // hidden (fp16)
__device__ float  g_eout[(size_t)ROWS_PAD * H_DIM];       // expert out (fp32)
__device__ __half g_w1h[(size_t)E_NUM * H_DIM * F_DIM];   // [E][K=H][N=F] fp16
__device__ __half g_w2h[(size_t)E_NUM * F_DIM * H_DIM];   // [E][K=F][N=H] fp16

// ---------------- init ----------------
__global__ void k_init() {
    int i = blockIdx.x * blockDim.x + threadIdx.x;
    if (i < ROWS_PAD) g_rowtok[i] = -1;
    if (i < E_NUM) { g_counts[i] = 0; g_cursor[i] = 0; }
}

// ---------------- fp32 -> fp16 converters (symbol destinations) ----------------
__device__ __forceinline__ uint4 cvt8(const float* __restrict__ src, int i) {
    const float4* s = (const float4*)src + i * 2;
    float4 u0 = s[0], u1 = s[1];
    __half2 h0 = __floats2half2_rn(u0.x, u0.y);
    __half2 h1 = __floats2half2_rn(u0.z, u0.w);
    __half2 h2 = __floats2half2_rn(u1.x, u1.y);
    __half2 h3 = __floats2half2_rn(u1.z, u1.w);
    uint4 o;
    o.x = reinterpret_cast<uint32_t&>(h0);
    o.y = reinterpret_cast<uint32_t&>(h1);
    o.z = reinterpret_cast<uint32_t&>(h2);
    o.w = reinterpret_cast<uint32_t&>(h3);
    return o;
}
__global__ void k_cvt_x(const float* __restrict__ src) {
    int i = blockIdx.x * blockDim.x + threadIdx.x;
    ((uint4*)g_xh)[i] = cvt8(src, i);
}
__global__ void k_cvt_w1(const float* __restrict__ src) {
    int i = blockIdx.x * blockDim.x + threadIdx.x;
    ((uint4*)g_w1h)[i] = cvt8(src, i);
}
__global__ void k_cvt_w2(const float* __restrict__ src) {
    int i = blockIdx.x * blockDim.x + threadIdx.x;
    ((uint4*)g_w2h)[i] = cvt8(src, i);
}

// ---------------- gating ----------------
__global__ void k_gate(const float* __restrict__ x, const float* __restrict__ gw,
                       const float* __restrict__ gb) {
    __shared__ float sgw[H_DIM * 17];
    int tid = threadIdx.x;
    for (int i = tid; i < H_DIM * E_NUM; i += 256) {
        int h = i >> 4, e = i & 15;
        sgw[h * 17 + e] = gw[i];
    }
    __syncthreads();
    int warp = tid >> 5, lane = tid & 31;
    int t = blockIdx.x * 8 + warp;
    float acc[E_NUM];
#pragma unroll
    for (int e = 0; e < E_NUM; e++) acc[e] = 0.f;
    const float* xr = x + (size_t)t * H_DIM;
#pragma unroll
    for (int c = 0; c < H_DIM / 32; c++) {
        int h = c * 32 + lane;
        float xv = xr[h];
#pragma unroll
        for (int e = 0; e < E_NUM; e++) acc[e] += xv * sgw[h * 17 + e];
    }
#pragma unroll
    for (int e = 0; e < E_NUM; e++) {
        float v = acc[e];
        v += __shfl_down_sync(0xffffffffu, v, 16);
        v += __shfl_down_sync(0xffffffffu, v, 8);
        v += __shfl_down_sync(0xffffffffu, v, 4);
        v += __shfl_down_sync(0xffffffffu, v, 2);
        v += __shfl_down_sync(0xffffffffu, v, 1);
        acc[e] = v;
    }
    if (lane == 0) {
        float logit[E_NUM];
#pragma unroll
        for (int e = 0; e < E_NUM; e++) logit[e] = acc[e] + gb[e];
        int i0 = 0; float m0 = logit[0];
#pragma unroll
        for (int e = 1; e < E_NUM; e++) if (logit[e] > m0) { m0 = logit[e]; i0 = e; }
        int i1 = -1; float m1 = -3.0e38f;
#pragma unroll
        for (int e = 0; e < E_NUM; e++)
            if (e != i0 && logit[e] > m1) { m1 = logit[e]; i1 = e; }
        float z = expf(m1 - m0);
        float w0 = 1.f / (1.f + z);
        float w1 = z * w0;
        g_eid[t * 2 + 0] = i0; g_eid[t * 2 + 1] = i1;
        g_gw[t * 2 + 0] = w0;  g_gw[t * 2 + 1] = w1;
        atomicAdd(&g_counts[i0], 1);
        atomicAdd(&g_counts[i1], 1);
    }
}

__global__ void k_scan() {
    if (threadIdx.x == 0) {
        int off = 0;
        g_poff[0] = 0;
        for (int e = 0; e < E_NUM; e++) {
            off += (g_counts[e] + 127) & ~127;
            g_poff[e + 1] = off;
        }
    }
}

__global__ void k_scatter() {
    int t = blockIdx.x * blockDim.x + threadIdx.x;
    if (t >= T_TOK) return;
#pragma unroll
    for (int k = 0; k < 2; k++) {
        int e = g_eid[t * 2 + k];
        int pos = atomicAdd(&g_cursor[e], 1);
        int row = g_poff[e] + pos;
        g_rowtok[row] = t;
        g_tokrow[t * 2 + k] = row;
    }
}

// ---------------- grouped GEMM: all-fp16, HFMA2, k-depth 16, double-buffered ----------------
// A tile 128x16 (per thread: one 16B slice), B tile 16x128 (per thread: one 16B slice).
// fp16 accumulators flushed to fp32 every 2 chunks (32 k-steps, same as verified R11).
template <int KDIM, int NDIM, bool GATHER, bool RELU>
__global__ __launch_bounds__(256, 2)
void k_gemm(const float* __restrict__ bias) {
    int r0 = blockIdx.x * 128;
    if (r0 >= g_poff[E_NUM]) return;
    int e = 0;
#pragma unroll
    for (int i = 1; i < E_NUM; i++) if (r0 >= g_poff[i]) e = i;

    const __half* Wb = (GATHER ? g_w1h : g_w2h) + (size_t)e * KDIM * NDIM;
    int n0 = blockIdx.y * 128;
    int tid = threadIdx.x;

    __shared__ __half As[2][16][128];
    __shared__ __half Bs[2][16][128];

    int arow = tid >> 1;
    int acol = (tid & 1) * 8;       // 8 halves = 16 B per thread
    int brow = tid >> 4;            // 0..15
    int bcol = (tid & 15) * 8;      // 8 halves = 16 B per thread

    const __half* Aptr;
    if (GATHER) {
        int tok = g_rowtok[r0 + arow];
        Aptr = (tok >= 0) ? (g_xh + (size_t)tok * KDIM + acol) : nullptr;
    } else {
        Aptr = g_h + (size_t)(r0 + arow) * KDIM + acol;
    }
    const __half* Wrow = Wb + (size_t)brow * NDIM + n0 + bcol;

    int ty = tid >> 4, tx = tid & 15;
    float accf[8][8];
#pragma unroll
    for (int i = 0; i < 8; i++)
#pragma unroll
        for (int j = 0; j < 8; j++) accf[i][j] = 0.f;

    __half2 acc2[8][4];
#pragma unroll
    for (int i = 0; i < 8; i++)
#pragma unroll
        for (int j = 0; j < 4; j++) acc2[i][j] = __float2half2_rn(0.f);

    constexpr int CHUNKS = KDIM / 16;

    // prologue: chunk 0 into buffer 0
    {
        uint4 avr = make_uint4(0u, 0u, 0u, 0u);
        if (!GATHER || Aptr) avr = *(const uint4*)(Aptr);
        const __half* hv = (const __half*)&avr;
#pragma unroll
        for (int i = 0; i < 8; i++) As[0][acol + i][arow] = hv[i];
        *(uint4*)&Bs[0][brow][bcol] = *(const uint4*)(Wrow);
    }
    __syncthreads();

    for (int c = 0; c < CHUNKS; c++) {
        const int b = c & 1;
        uint4 avr, bwr;
        const bool more = (c + 1 < CHUNKS);
        if (more) {
            avr = make_uint4(0u, 0u, 0u, 0u);
            if (!GATHER || Aptr) avr = *(const uint4*)(Aptr + (c + 1) * 16);
            bwr = *(const uint4*)(Wrow + (size_t)(c + 1) * 16 * NDIM);
        }

#pragma unroll
        for (int k = 0; k < 16; k++) {
            __half2 a2[8];
            {
                uint4 ap = *(const uint4*)&As[b][k][ty * 8];
                __half2 q0 = reinterpret_cast<__half2&>(ap.x);
                __half2 q1 = reinterpret_cast<__half2&>(ap.y);
                __half2 q2 = reinterpret_cast<__half2&>(ap.z);
                __half2 q3 = reinterpret_cast<__half2&>(ap.w);
                a2[0] = __low2half2(q0);  a2[1] = __high2half2(q0);
                a2[2] = __low2half2(q1);  a2[3] = __high2half2(q1);
                a2[4] = __low2half2(q2);  a2[5] = __high2half2(q2);
                a2[6] = __low2half2(q3);  a2[7] = __high2half2(q3);
            }
            __half2 b2[4];
            {
                uint4 bp = *(const uint4*)&Bs[b][k][tx * 8];
                b2[0] = reinterpret_cast<__half2&>(bp.x);
                b2[1] = reinterpret_cast<__half2&>(bp.y);
                b2[2] = reinterpret_cast<__half2&>(bp.z);
                b2[3] = reinterpret_cast<__half2&>(bp.w);
            }
#pragma unroll
            for (int i = 0; i < 8; i++)
#pragma unroll
                for (int j = 0; j < 4; j++)
                    acc2[i][j] = __hfma2(a2[i], b2[j], acc2[i][j]);
        }

        if ((c & 1) == 1) {   // flush fp16 window -> fp32 every 32 k-steps
#pragma unroll
            for (int i = 0; i < 8; i++)
#pragma unroll
                for (int j = 0; j < 4; j++) {
                    float2 f = __half22float2(acc2[i][j]);
                    accf[i][j * 2 + 0] += f.x;
                    accf[i][j * 2 + 1] += f.y;
                    acc2[i][j] = __float2half2_rn(0.f);
                }
        }

        if (more) {
            const int nb = 1 - b;
            const __half* hv = (const __half*)&avr;
#pragma unroll
            for (int i = 0; i < 8; i++) As[nb][acol + i][arow] = hv[i];
            *(uint4*)&Bs[nb][brow][bcol] = bwr;
            __syncthreads();
        }
    }

    float bv[8];
#pragma unroll
    for (int j = 0; j < 8; j++) bv[j] = bias[(size_t)e * NDIM + n0 + tx * 8 + j];

#pragma unroll
    for (int i = 0; i < 8; i++) {
        int r = r0 + ty * 8 + i;
        float o[8];
#pragma unroll
        for (int j = 0; j < 8; j++) {
            float v = accf[i][j] + bv[j];
            if (RELU) v = fmaxf(v, 0.f);
            o[j] = v;
        }
        if (RELU) {
            __half2 h0 = __floats2half2_rn(o[0], o[1]);
            __half2 h1 = __floats2half2_rn(o[2], o[3]);
            __half2 h2 = __floats2half2_rn(o[4], o[5]);
            __half2 h3 = __floats2half2_rn(o[6], o[7]);
            uint4 pk;
            pk.x = reinterpret_cast<uint32_t&>(h0);
            pk.y = reinterpret_cast<uint32_t&>(h1);
            pk.z = reinterpret_cast<uint32_t&>(h2);
            pk.w = reinterpret_cast<uint32_t&>(h3);
            *(uint4*)(g_h + (size_t)r * NDIM + n0 + tx * 8) = pk;
        } else {
            float* cp = g_eout + (size_t)r * NDIM + n0 + tx * 8;
            *(float4*)&cp[0] = *(float4*)&o[0];
            *(float4*)&cp[4] = *(float4*)&o[4];
        }
    }
}

// ---------------- combine + residual + LayerNorm ----------------
__global__ void k_combine_ln(const float* __restrict__ x,
                             const float* __restrict__ gamma,
                             const float* __restrict__ beta,
                             float* __restrict__ out) {
    int warp = threadIdx.x >> 5, lane = threadIdx.x & 31;
    int t = blockIdx.x * 8 + warp;
    int row0 = g_tokrow[t * 2 + 0];
    int row1 = g_tokrow[t * 2 + 1];
    float w0 = g_gw[t * 2 + 0];
    float w1 = g_gw[t * 2 + 1];
    const float* xr = x + (size_t)t * H_DIM;
    const float* o0 = g_eout + (size_t)row0 * H_DIM;
    const float* o1 = g_eout + (size_t)row1 * H_DIM;

    float v[8];
    float s = 0.f, sq = 0.f;
#pragma unroll
    for (int j = 0; j < 8; j++) {
        int h = j * 32 + lane;
        float y = xr[h] + w0 * o0[h] + w1 * o1[h];
        v[j] = y;
        s += y;
        sq += y * y;
    }
#pragma unroll
    for (int off = 16; off > 0; off >>= 1) {
        s  += __shfl_xor_sync(0xffffffffu, s, off);
        sq += __shfl_xor_sync(0xffffffffu, sq, off);
    }
    float mu = s * (1.f / H_DIM);
    float var = sq * (1.f / H_DIM) - mu * mu;
    float rs = rsqrtf(var + 1e-5f);
    float* outr = out + (size_t)t * H_DIM;
#pragma unroll
    for (int j = 0; j < 8; j++) {
        int h = j * 32 + lane;
        outr[h] = (v[j] - mu) * rs * gamma[h] + beta[h];
    }
}

// ---------------- launch ----------------
extern "C" void kernel_launch(void* const* d_in, const int* in_sizes, int n_in,
                              void* d_out, int out_size) {
    const float* x      = (const float*)d_in[0];
    const float* gate_w = (const float*)d_in[1];
    const float* gate_b = (const float*)d_in[2];
    const float* w1     = (const float*)d_in[3];
    const float* b1     = (const float*)d_in[4];
    const float* w2     = (const float*)d_in[5];
    const float* b2     = (const float*)d_in[6];
    const float* gamma  = (const float*)d_in[7];
    const float* beta   = (const float*)d_in[8];
    float* out = (float*)d_out;

    k_init<<<(ROWS_PAD + 255) / 256, 256>>>();
    k_cvt_x <<<T_TOK * H_DIM / 8 / 256, 256>>>(x);
    k_cvt_w1<<<E_NUM * H_DIM * F_DIM / 8 / 256, 256>>>(w1);
    k_cvt_w2<<<E_NUM * F_DIM * H_DIM / 8 / 256, 256>>>(w2);
    k_gate<<<T_TOK / 8, 256>>>(x, gate_w, gate_b);
    k_scan<<<1, 32>>>();
    k_scatter<<<T_TOK / 256, 256>>>();
    k_gemm<H_DIM, F_DIM, true,  true ><<<dim3(MAXT, F_DIM / 128), 256>>>(b1);
    k_gemm<F_DIM, H_DIM, false, false><<<dim3(MAXT, H_DIM / 128), 256>>>(b2);
    k_combine_ln<<<T_TOK / 8, 256>>>(x, gamma, beta, out);
}